// round 1
// baseline (speedup 1.0000x reference)
#include <cuda_runtime.h>

#define N_NODES 4096
#define IN_F    512
#define OUT_F   1024
#define HEADS   8
#define HEAD_F  128

// Scratch (device globals — no allocation allowed)
__device__ float g_h [N_NODES * OUT_F];   // h laid out [n][head*128+f]
__device__ float g_ci[HEADS * N_NODES];
__device__ float g_cj[HEADS * N_NODES];

// ---------------------------------------------------------------------------
// GEMM: C[4096,1024] = A[4096,512] @ B   (MODE 0: B = W[h][k][f] -> g_h,
//                                         MODE 1: B = W_r row-major, +bias -> out)
// Tile: BM=64, BN=128, BK=32; 256 threads, each 4x8 outputs.
// ---------------------------------------------------------------------------
template <int MODE>
__global__ __launch_bounds__(256) void gemm_kernel(
    const float* __restrict__ A, const float* __restrict__ B,
    const float* __restrict__ bias, float* __restrict__ C)
{
    constexpr int BM = 64, BN = 128, BK = 32;
    __shared__ float As[BM][36];   // padded: 16B-aligned f4 stores, conflict-free scalar reads
    __shared__ float Bs[BK][BN];

    const int t  = threadIdx.x;
    const int tx = t & 15, ty = t >> 4;
    const int row0 = blockIdx.x * BM;
    const int o0   = blockIdx.y * BN;   // MODE 0: blockIdx.y == head (BN==HEAD_F? no, BN=128==HEAD_F, yes)

    float acc[4][8];
#pragma unroll
    for (int i = 0; i < 4; i++)
#pragma unroll
        for (int j = 0; j < 8; j++) acc[i][j] = 0.f;

    for (int k0 = 0; k0 < IN_F; k0 += BK) {
        // A tile: 64x32 = 512 float4
#pragma unroll
        for (int i = 0; i < 2; i++) {
            int f4 = t + i * 256;
            int r = f4 >> 3, kk4 = f4 & 7;
            float4 v = *(const float4*)&A[(row0 + r) * IN_F + k0 + kk4 * 4];
            *(float4*)&As[r][kk4 * 4] = v;
        }
        // B tile: 32x128 = 1024 float4
#pragma unroll
        for (int i = 0; i < 4; i++) {
            int f4 = t + i * 256;
            int k = f4 >> 5, c4 = f4 & 31;
            float4 v;
            if (MODE == 0) {
                // W[head][k][f], head = blockIdx.y, 128 floats contiguous per (head,k)
                v = *(const float4*)&B[blockIdx.y * (IN_F * HEAD_F) + (k0 + k) * HEAD_F + c4 * 4];
            } else {
                v = *(const float4*)&B[(k0 + k) * OUT_F + o0 + c4 * 4];
            }
            *(float4*)&Bs[k][c4 * 4] = v;
        }
        __syncthreads();

#pragma unroll
        for (int k = 0; k < BK; k++) {
            float a[4];
#pragma unroll
            for (int i = 0; i < 4; i++) a[i] = As[ty * 4 + i][k];
            float4 b0 = *(const float4*)&Bs[k][tx * 8];
            float4 b1 = *(const float4*)&Bs[k][tx * 8 + 4];
#pragma unroll
            for (int i = 0; i < 4; i++) {
                acc[i][0] += a[i] * b0.x; acc[i][1] += a[i] * b0.y;
                acc[i][2] += a[i] * b0.z; acc[i][3] += a[i] * b0.w;
                acc[i][4] += a[i] * b1.x; acc[i][5] += a[i] * b1.y;
                acc[i][6] += a[i] * b1.z; acc[i][7] += a[i] * b1.w;
            }
        }
        __syncthreads();
    }

#pragma unroll
    for (int i = 0; i < 4; i++) {
        int r = row0 + ty * 4 + i;
        int c = o0 + tx * 8;
        float4 v0 = make_float4(acc[i][0], acc[i][1], acc[i][2], acc[i][3]);
        float4 v1 = make_float4(acc[i][4], acc[i][5], acc[i][6], acc[i][7]);
        float* dst = (MODE == 0) ? g_h : C;
        if (MODE == 1) {
            v0.x += bias[c];     v0.y += bias[c + 1];
            v0.z += bias[c + 2]; v0.w += bias[c + 3];
            v1.x += bias[c + 4]; v1.y += bias[c + 5];
            v1.z += bias[c + 6]; v1.w += bias[c + 7];
        }
        *(float4*)&dst[r * OUT_F + c]     = v0;
        *(float4*)&dst[r * OUT_F + c + 4] = v1;
    }
}

// ---------------------------------------------------------------------------
// coe_i[h,n] = h[h,n,:]·w_i[h],  coe_j[h,n] = h[h,n,:]·w_j[h]
// One warp per (n, head).
// ---------------------------------------------------------------------------
__global__ void coe_kernel(const float* __restrict__ wi, const float* __restrict__ wj)
{
    int n = blockIdx.x, h = blockIdx.y, lane = threadIdx.x;
    float4 hv = *(const float4*)&g_h[n * OUT_F + h * HEAD_F + lane * 4];
    float4 a  = *(const float4*)&wi[h * HEAD_F + lane * 4];
    float4 b  = *(const float4*)&wj[h * HEAD_F + lane * 4];
    float si = hv.x * a.x + hv.y * a.y + hv.z * a.z + hv.w * a.w;
    float sj = hv.x * b.x + hv.y * b.y + hv.z * b.z + hv.w * b.w;
#pragma unroll
    for (int o = 16; o; o >>= 1) {
        si += __shfl_xor_sync(0xffffffffu, si, o);
        sj += __shfl_xor_sync(0xffffffffu, sj, o);
    }
    if (lane == 0) {
        g_ci[h * N_NODES + n] = si;
        g_cj[h * N_NODES + n] = sj;
    }
}

// ---------------------------------------------------------------------------
// Flash-style masked attention + P@h accumulate + residual add.
// Block: 256 threads handles BN=64 query rows for one head.
// Thread t: feature group fg = t&15 (8 feats), row set rs = t>>4 (4 rows).
// out[n, h*128+f] += (softmax row n) @ h[:, h*128+f]
// ---------------------------------------------------------------------------
__global__ __launch_bounds__(256) void attn_kernel(
    const int* __restrict__ graph, float* __restrict__ out)
{
    constexpr int BN = 64, BM = 32;
    __shared__ float h_s[BM][HEAD_F];       // 16 KB
    __shared__ float p_s[BN][BM + 1];       // padded vs bank conflicts
    __shared__ float ci_s[BN], cj_s[BM];
    __shared__ float rmax_s[BN], rsum_s[BN], rsc_s[BN];

    const int t = threadIdx.x;
    const int n0 = blockIdx.x * BN;
    const int head = blockIdx.y;
    const int fg = t & 15, rs = t >> 4;

    if (t < BN) {
        ci_s[t]   = g_ci[head * N_NODES + n0 + t];
        rmax_s[t] = -1e30f;
        rsum_s[t] = 0.f;
    }

    float acc[4][8];
#pragma unroll
    for (int i = 0; i < 4; i++)
#pragma unroll
        for (int j = 0; j < 8; j++) acc[i][j] = 0.f;

    for (int m0 = 0; m0 < N_NODES; m0 += BM) {
        __syncthreads();   // protect h_s/p_s reuse (and ci_s init on first iter)

        // load key tile h[m0:m0+32, head*128:+128]  (32x128 = 1024 f4)
#pragma unroll
        for (int i = 0; i < 4; i++) {
            int f4 = t + i * 256;
            int r = f4 >> 5, c4 = f4 & 31;
            *(float4*)&h_s[r][c4 * 4] =
                *(const float4*)&g_h[(m0 + r) * OUT_F + head * HEAD_F + c4 * 4];
        }
        if (t < BM) cj_s[t] = g_cj[head * N_NODES + m0 + t];
        __syncthreads();

        // logits: s = leaky_relu(ci+cj), masked by graph[m][n] (graph.T)
#pragma unroll
        for (int i = 0; i < 8; i++) {
            int idx = i * 256 + t;
            int m = idx >> 6, row = idx & 63;
            float s = ci_s[row] + cj_s[m];
            s = s > 0.f ? s : 0.2f * s;
            int g = graph[(m0 + m) * N_NODES + n0 + row];
            p_s[row][m] = (g > 0) ? s : -1e30f;
        }
        __syncthreads();

        // per-row running max + rescale factor
        if (t < BN) {
            float mx = rmax_s[t];
#pragma unroll
            for (int m = 0; m < BM; m++) mx = fmaxf(mx, p_s[t][m]);
            float f = __expf(rmax_s[t] - mx);
            rsc_s[t] = f;
            rsum_s[t] *= f;
            rmax_s[t] = mx;
        }
        __syncthreads();

        // exponentiate in place; rescale register accumulators
#pragma unroll
        for (int i = 0; i < 8; i++) {
            int idx = i * 256 + t;
            int m = idx >> 6, row = idx & 63;
            p_s[row][m] = __expf(p_s[row][m] - rmax_s[row]);
        }
#pragma unroll
        for (int i = 0; i < 4; i++) {
            float f = rsc_s[rs * 4 + i];
#pragma unroll
            for (int j = 0; j < 8; j++) acc[i][j] *= f;
        }
        __syncthreads();

        // accumulate acc += p * h  (FMA-bound main loop)
#pragma unroll
        for (int m = 0; m < BM; m++) {
            float4 hv0 = *(const float4*)&h_s[m][fg * 8];
            float4 hv1 = *(const float4*)&h_s[m][fg * 8 + 4];
#pragma unroll
            for (int i = 0; i < 4; i++) {
                float p = p_s[rs * 4 + i][m];
                acc[i][0] += p * hv0.x; acc[i][1] += p * hv0.y;
                acc[i][2] += p * hv0.z; acc[i][3] += p * hv0.w;
                acc[i][4] += p * hv1.x; acc[i][5] += p * hv1.y;
                acc[i][6] += p * hv1.z; acc[i][7] += p * hv1.w;
            }
        }
        // running denominator
        if (t < BN) {
            float s = 0.f;
#pragma unroll
            for (int m = 0; m < BM; m++) s += p_s[t][m];
            rsum_s[t] += s;
        }
    }
    __syncthreads();

    // finalize: out += acc / rsum (out already holds x@W_r + bias)
#pragma unroll
    for (int i = 0; i < 4; i++) {
        int row = rs * 4 + i;
        float inv = 1.f / rsum_s[row];
        int idx = (n0 + row) * OUT_F + head * HEAD_F + fg * 8;
        float4 o0 = *(float4*)&out[idx];
        float4 o1 = *(float4*)&out[idx + 4];
        o0.x += acc[i][0] * inv; o0.y += acc[i][1] * inv;
        o0.z += acc[i][2] * inv; o0.w += acc[i][3] * inv;
        o1.x += acc[i][4] * inv; o1.y += acc[i][5] * inv;
        o1.z += acc[i][6] * inv; o1.w += acc[i][7] * inv;
        *(float4*)&out[idx]     = o0;
        *(float4*)&out[idx + 4] = o1;
    }
}

// ---------------------------------------------------------------------------
extern "C" void kernel_launch(void* const* d_in, const int* in_sizes, int n_in,
                              void* d_out, int out_size)
{
    const float* x     = (const float*)d_in[0];
    const int*   graph = (const int*)  d_in[1];
    const float* W     = (const float*)d_in[2];
    const float* w_i   = (const float*)d_in[3];
    const float* w_j   = (const float*)d_in[4];
    const float* W_r   = (const float*)d_in[5];
    const float* bias  = (const float*)d_in[6];
    float* out = (float*)d_out;

    // h = x @ W (all heads fused as one [4096,512]x[512,1024] GEMM) -> g_h
    gemm_kernel<0><<<dim3(N_NODES / 64, OUT_F / 128), 256>>>(x, W, nullptr, nullptr);
    // out = x @ W_r + bias  (residual written first; attention adds into it)
    gemm_kernel<1><<<dim3(N_NODES / 64, OUT_F / 128), 256>>>(x, W_r, bias, out);
    // attention coefficients
    coe_kernel<<<dim3(N_NODES, HEADS), 32>>>(w_i, w_j);
    // masked softmax attention + P@h + residual combine
    attn_kernel<<<dim3(N_NODES / 64, HEADS), 256>>>(graph, out);
}

// round 3
// speedup vs baseline: 1.3981x; 1.3981x over previous
#include <cuda_runtime.h>

#define N_NODES 4096
#define IN_F    512
#define OUT_F   1024
#define HEADS   8
#define HEAD_F  128

// Scratch (device globals — no allocation allowed)
__device__ float  g_h  [N_NODES * OUT_F];      // h laid out [n][head*128+f]
__device__ float4 g_ci4[HEADS * N_NODES];      // (ci, e^ci, e^{0.2 ci}, -)
__device__ float4 g_cj4[HEADS * N_NODES];      // (cj, e^cj, e^{0.2 cj}, -)

// ---- packed fp32x2 helpers (sm_103a FFMA2) --------------------------------
__device__ __forceinline__ void ffma2(unsigned long long& d,
                                      unsigned long long a,
                                      unsigned long long b) {
    asm("fma.rn.f32x2 %0, %1, %2, %0;" : "+l"(d) : "l"(a), "l"(b));
}
__device__ __forceinline__ unsigned long long pack2(float x) {
    unsigned long long r;
    asm("mov.b64 %0, {%1, %1};" : "=l"(r) : "f"(x));
    return r;
}
__device__ __forceinline__ float2 unpack2(unsigned long long u) {
    float2 f;
    asm("mov.b64 {%0, %1}, %2;" : "=f"(f.x), "=f"(f.y) : "l"(u));
    return f;
}

// ---------------------------------------------------------------------------
// GEMM: C[4096,1024] = A[4096,512] @ B
//   MODE 0: B = W[h][k][f] (head-blocked)  -> g_h
//   MODE 1: B = W_r row-major, + bias      -> out
// Tile BM=64, BN=128, BK=32; 256 threads, 4x8 outputs/thread, FFMA2 inner.
// ---------------------------------------------------------------------------
template <int MODE>
__global__ __launch_bounds__(256) void gemm_kernel(
    const float* __restrict__ A, const float* __restrict__ B,
    const float* __restrict__ bias, float* __restrict__ C)
{
    constexpr int BM = 64, BN = 128, BK = 32;
    __shared__ float As[BM][36];
    __shared__ float Bs[BK][BN];

    const int t  = threadIdx.x;
    const int tx = t & 15, ty = t >> 4;
    const int row0 = blockIdx.x * BM;
    const int o0   = blockIdx.y * BN;

    unsigned long long acc[4][4];
#pragma unroll
    for (int i = 0; i < 4; i++)
#pragma unroll
        for (int j = 0; j < 4; j++) acc[i][j] = 0ull;

    for (int k0 = 0; k0 < IN_F; k0 += BK) {
#pragma unroll
        for (int i = 0; i < 2; i++) {
            int f4 = t + i * 256;
            int r = f4 >> 3, kk4 = f4 & 7;
            float4 v = *(const float4*)&A[(row0 + r) * IN_F + k0 + kk4 * 4];
            *(float4*)&As[r][kk4 * 4] = v;
        }
#pragma unroll
        for (int i = 0; i < 4; i++) {
            int f4 = t + i * 256;
            int k = f4 >> 5, c4 = f4 & 31;
            float4 v;
            if (MODE == 0)
                v = *(const float4*)&B[blockIdx.y * (IN_F * HEAD_F) + (k0 + k) * HEAD_F + c4 * 4];
            else
                v = *(const float4*)&B[(k0 + k) * OUT_F + o0 + c4 * 4];
            *(float4*)&Bs[k][c4 * 4] = v;
        }
        __syncthreads();

#pragma unroll
        for (int k = 0; k < BK; k++) {
            unsigned long long av[4];
#pragma unroll
            for (int i = 0; i < 4; i++) av[i] = pack2(As[ty * 4 + i][k]);
            ulonglong2 b0 = *(const ulonglong2*)&Bs[k][tx * 8];
            ulonglong2 b1 = *(const ulonglong2*)&Bs[k][tx * 8 + 4];
#pragma unroll
            for (int i = 0; i < 4; i++) {
                ffma2(acc[i][0], av[i], b0.x);
                ffma2(acc[i][1], av[i], b0.y);
                ffma2(acc[i][2], av[i], b1.x);
                ffma2(acc[i][3], av[i], b1.y);
            }
        }
        __syncthreads();
    }

#pragma unroll
    for (int i = 0; i < 4; i++) {
        int r = row0 + ty * 4 + i;
        int c = o0 + tx * 8;
        float2 a0 = unpack2(acc[i][0]), a1 = unpack2(acc[i][1]);
        float2 a2 = unpack2(acc[i][2]), a3 = unpack2(acc[i][3]);
        float4 v0 = make_float4(a0.x, a0.y, a1.x, a1.y);
        float4 v1 = make_float4(a2.x, a2.y, a3.x, a3.y);
        float* dst = (MODE == 0) ? g_h : C;
        if (MODE == 1) {
            v0.x += bias[c];     v0.y += bias[c + 1];
            v0.z += bias[c + 2]; v0.w += bias[c + 3];
            v1.x += bias[c + 4]; v1.y += bias[c + 5];
            v1.z += bias[c + 6]; v1.w += bias[c + 7];
        }
        *(float4*)&dst[r * OUT_F + c]     = v0;
        *(float4*)&dst[r * OUT_F + c + 4] = v1;
    }
}

// ---------------------------------------------------------------------------
// coe: per (head,n) dot products + precomputed exponentials.
// 256 threads = 8 warps; warp w handles node blockIdx.x*8+w for head blockIdx.y.
// ---------------------------------------------------------------------------
__global__ __launch_bounds__(256) void coe_kernel(
    const float* __restrict__ wi, const float* __restrict__ wj)
{
    int w = threadIdx.x >> 5, lane = threadIdx.x & 31;
    int n = blockIdx.x * 8 + w, h = blockIdx.y;
    float4 hv = *(const float4*)&g_h[n * OUT_F + h * HEAD_F + lane * 4];
    float4 a  = *(const float4*)&wi[h * HEAD_F + lane * 4];
    float4 b  = *(const float4*)&wj[h * HEAD_F + lane * 4];
    float si = hv.x * a.x + hv.y * a.y + hv.z * a.z + hv.w * a.w;
    float sj = hv.x * b.x + hv.y * b.y + hv.z * b.z + hv.w * b.w;
#pragma unroll
    for (int o = 16; o; o >>= 1) {
        si += __shfl_xor_sync(0xffffffffu, si, o);
        sj += __shfl_xor_sync(0xffffffffu, sj, o);
    }
    if (lane == 0) {
        g_ci4[h * N_NODES + n] = make_float4(si, __expf(si), __expf(0.2f * si), 0.f);
        g_cj4[h * N_NODES + n] = make_float4(sj, __expf(sj), __expf(0.2f * sj), 0.f);
    }
}

// ---------------------------------------------------------------------------
// Attention (no online softmax needed: logits bounded, so raw exp is safe and
// the per-row normalizer cancels exactly vs the reference's max-subtraction).
//   P[n][m] = graph[m][n] * (ci+cj>0 ? e^ci e^cj : e^{.2ci} e^{.2cj})
//   out[n][h*128+f] += (Σ_m P·h[m][f]) / (Σ_m P)
// Block: 256 thr, BN=128 rows, BM=32 keys/tile.
//   logit phase: thread -> (row = t&127, parity b = t>>7), 16 keys each
//   fma phase:   thread -> (fg = t&15 -> 8 feats, rs = t>>4 -> 8 rows), FFMA2
// ---------------------------------------------------------------------------
__global__ __launch_bounds__(256, 2) void attn_kernel(
    const int* __restrict__ graph, float* __restrict__ out)
{
    constexpr int BN = 128, BM = 32;
    __shared__ float h_s[BM][HEAD_F];        // 16 KB
    __shared__ float p_s[BN][BM + 2];        // stride 34: float2-aligned rows
    __shared__ float sum_s[2][BN];

    const int t    = threadIdx.x;
    const int n0   = blockIdx.x * BN;
    const int head = blockIdx.y;

    const int lrow = t & 127;
    const int lb   = t >> 7;                 // key parity 0/1
    const float4 ci4 = g_ci4[head * N_NODES + n0 + lrow];
    const float4* __restrict__ cj4p = &g_cj4[head * N_NODES];
    float rsum = 0.f;

    const int fg = t & 15, rs = t >> 4;

    unsigned long long acc[8][4];
#pragma unroll
    for (int i = 0; i < 8; i++)
#pragma unroll
        for (int j = 0; j < 4; j++) acc[i][j] = 0ull;

    for (int m0 = 0; m0 < N_NODES; m0 += BM) {
        __syncthreads();
        // load key tile h[m0:m0+32]
#pragma unroll
        for (int i = 0; i < 4; i++) {
            int f4 = t + i * 256;
            int r = f4 >> 5, c4 = f4 & 31;
            *(float4*)&h_s[r][c4 * 4] =
                *(const float4*)&g_h[(m0 + r) * OUT_F + head * HEAD_F + c4 * 4];
        }
        // logits -> p_s (exp-free: precomputed exponentials, factorized lrelu)
#pragma unroll
        for (int e = 0; e < 16; e++) {
            int m = 2 * e + lb;
            float4 cj4 = __ldg(&cj4p[m0 + m]);
            int g = __ldg(&graph[(m0 + m) * N_NODES + n0 + lrow]);
            float s = ci4.x + cj4.x;
            float pa = s > 0.f ? ci4.y : ci4.z;
            float pb = s > 0.f ? cj4.y : cj4.z;
            float p = pa * pb * (float)g;
            p_s[lrow][m] = p;
            rsum += p;
        }
        __syncthreads();
        // acc += P * h   (FFMA2, key pairs)
#pragma unroll
        for (int mb = 0; mb < 16; mb++) {
            ulonglong2 h0a = *(const ulonglong2*)&h_s[2 * mb][fg * 8];
            ulonglong2 h0b = *(const ulonglong2*)&h_s[2 * mb][fg * 8 + 4];
            ulonglong2 h1a = *(const ulonglong2*)&h_s[2 * mb + 1][fg * 8];
            ulonglong2 h1b = *(const ulonglong2*)&h_s[2 * mb + 1][fg * 8 + 4];
#pragma unroll
            for (int i = 0; i < 8; i++) {
                float2 pp = *(const float2*)&p_s[rs * 8 + i][2 * mb];
                unsigned long long p0 = pack2(pp.x);
                unsigned long long p1 = pack2(pp.y);
                ffma2(acc[i][0], p0, h0a.x);
                ffma2(acc[i][1], p0, h0a.y);
                ffma2(acc[i][2], p0, h0b.x);
                ffma2(acc[i][3], p0, h0b.y);
                ffma2(acc[i][0], p1, h1a.x);
                ffma2(acc[i][1], p1, h1a.y);
                ffma2(acc[i][2], p1, h1b.x);
                ffma2(acc[i][3], p1, h1b.y);
            }
        }
    }
    __syncthreads();
    sum_s[lb][lrow] = rsum;
    __syncthreads();

#pragma unroll
    for (int i = 0; i < 8; i++) {
        int r = rs * 8 + i;
        float inv = 1.f / (sum_s[0][r] + sum_s[1][r]);
        int idx = (n0 + r) * OUT_F + head * HEAD_F + fg * 8;
        float4 o0 = *(float4*)&out[idx];
        float4 o1 = *(float4*)&out[idx + 4];
        float2 a0 = unpack2(acc[i][0]), a1 = unpack2(acc[i][1]);
        float2 a2 = unpack2(acc[i][2]), a3 = unpack2(acc[i][3]);
        o0.x += a0.x * inv; o0.y += a0.y * inv;
        o0.z += a1.x * inv; o0.w += a1.y * inv;
        o1.x += a2.x * inv; o1.y += a2.y * inv;
        o1.z += a3.x * inv; o1.w += a3.y * inv;
        *(float4*)&out[idx]     = o0;
        *(float4*)&out[idx + 4] = o1;
    }
}

// ---------------------------------------------------------------------------
extern "C" void kernel_launch(void* const* d_in, const int* in_sizes, int n_in,
                              void* d_out, int out_size)
{
    const float* x     = (const float*)d_in[0];
    const int*   graph = (const int*)  d_in[1];
    const float* W     = (const float*)d_in[2];
    const float* w_i   = (const float*)d_in[3];
    const float* w_j   = (const float*)d_in[4];
    const float* W_r   = (const float*)d_in[5];
    const float* bias  = (const float*)d_in[6];
    float* out = (float*)d_out;

    gemm_kernel<0><<<dim3(N_NODES / 64, OUT_F / 128), 256>>>(x, W, nullptr, nullptr);
    gemm_kernel<1><<<dim3(N_NODES / 64, OUT_F / 128), 256>>>(x, W_r, bias, out);
    coe_kernel<<<dim3(N_NODES / 8, HEADS), 256>>>(w_i, w_j);
    attn_kernel<<<dim3(N_NODES / 128, HEADS), 256>>>(graph, out);
}

// round 6
// speedup vs baseline: 3.0597x; 2.1885x over previous
#include <cuda_runtime.h>
#include <cuda_bf16.h>

#define N_NODES 4096
#define IN_F    512
#define OUT_F   1024
#define HEADS   8
#define HEAD_F  128

// Scratch (device globals — no allocation allowed)
__device__ float          g_h    [N_NODES * OUT_F];            // h [n][head*128+f]
__device__ float4         g_ci4  [HEADS * N_NODES];            // (ci, e^ci, e^{0.2ci}, -)
__device__ float4         g_cj4  [HEADS * N_NODES];            // (cj, e^cj, e^{0.2cj}, -)
__device__ unsigned short g_hT16 [OUT_F * N_NODES];            // bf16 h^T [head*128+f][n]
__device__ unsigned int   g_maskT[(N_NODES / 32) * N_NODES];   // word [mw][n], bit j = graph[mw*32+j][n]>0

// ---- packed fp32x2 helpers (FFMA2, used by the fp32 GEMMs) ----------------
__device__ __forceinline__ void ffma2(unsigned long long& d, unsigned long long a,
                                      unsigned long long b) {
    asm("fma.rn.f32x2 %0, %1, %2, %0;" : "+l"(d) : "l"(a), "l"(b));
}
__device__ __forceinline__ unsigned long long pack2(float x) {
    unsigned long long r;
    asm("mov.b64 %0, {%1, %1};" : "=l"(r) : "f"(x));
    return r;
}
__device__ __forceinline__ float2 unpack2(unsigned long long u) {
    float2 f;
    asm("mov.b64 {%0, %1}, %2;" : "=f"(f.x), "=f"(f.y) : "l"(u));
    return f;
}

// ---- mma.sync m16n8k16 bf16 (portable PTX; fallback HMMA on sm_103) -------
__device__ __forceinline__ void mma_bf16(float* d, const unsigned* a,
                                         unsigned b0, unsigned b1) {
    asm volatile(
        "mma.sync.aligned.m16n8k16.row.col.f32.bf16.bf16.f32 "
        "{%0,%1,%2,%3}, {%4,%5,%6,%7}, {%8,%9}, {%0,%1,%2,%3};"
        : "+f"(d[0]), "+f"(d[1]), "+f"(d[2]), "+f"(d[3])
        : "r"(a[0]), "r"(a[1]), "r"(a[2]), "r"(a[3]), "r"(b0), "r"(b1));
}
__device__ __forceinline__ unsigned pack_bf16x2(float lo, float hi) {
    unsigned u;
    asm("cvt.rn.bf16x2.f32 %0, %1, %2;" : "=r"(u) : "f"(hi), "f"(lo));
    return u;
}
__device__ __forceinline__ float2 unpack_bf16x2(unsigned u) {
    // returns (lo, hi) as floats
    float2 r;
    unsigned lo = u << 16, hi = u & 0xffff0000u;
    r.x = __uint_as_float(lo);
    r.y = __uint_as_float(hi);
    return r;
}

// ---------------------------------------------------------------------------
// GEMM: C[4096,1024] = A[4096,512] @ B  (MODE 0 -> g_h, MODE 1 -> out +bias)
// ---------------------------------------------------------------------------
template <int MODE>
__global__ __launch_bounds__(256) void gemm_kernel(
    const float* __restrict__ A, const float* __restrict__ B,
    const float* __restrict__ bias, float* __restrict__ C)
{
    constexpr int BM = 64, BN = 128, BK = 32;
    __shared__ float As[BM][36];
    __shared__ float Bs[BK][BN];

    const int t  = threadIdx.x;
    const int tx = t & 15, ty = t >> 4;
    const int row0 = blockIdx.x * BM;
    const int o0   = blockIdx.y * BN;

    unsigned long long acc[4][4];
#pragma unroll
    for (int i = 0; i < 4; i++)
#pragma unroll
        for (int j = 0; j < 4; j++) acc[i][j] = 0ull;

    for (int k0 = 0; k0 < IN_F; k0 += BK) {
#pragma unroll
        for (int i = 0; i < 2; i++) {
            int f4 = t + i * 256;
            int r = f4 >> 3, kk4 = f4 & 7;
            float4 v = *(const float4*)&A[(row0 + r) * IN_F + k0 + kk4 * 4];
            *(float4*)&As[r][kk4 * 4] = v;
        }
#pragma unroll
        for (int i = 0; i < 4; i++) {
            int f4 = t + i * 256;
            int k = f4 >> 5, c4 = f4 & 31;
            float4 v;
            if (MODE == 0)
                v = *(const float4*)&B[blockIdx.y * (IN_F * HEAD_F) + (k0 + k) * HEAD_F + c4 * 4];
            else
                v = *(const float4*)&B[(k0 + k) * OUT_F + o0 + c4 * 4];
            *(float4*)&Bs[k][c4 * 4] = v;
        }
        __syncthreads();

#pragma unroll
        for (int k = 0; k < BK; k++) {
            unsigned long long av[4];
#pragma unroll
            for (int i = 0; i < 4; i++) av[i] = pack2(As[ty * 4 + i][k]);
            ulonglong2 b0 = *(const ulonglong2*)&Bs[k][tx * 8];
            ulonglong2 b1 = *(const ulonglong2*)&Bs[k][tx * 8 + 4];
#pragma unroll
            for (int i = 0; i < 4; i++) {
                ffma2(acc[i][0], av[i], b0.x);
                ffma2(acc[i][1], av[i], b0.y);
                ffma2(acc[i][2], av[i], b1.x);
                ffma2(acc[i][3], av[i], b1.y);
            }
        }
        __syncthreads();
    }

#pragma unroll
    for (int i = 0; i < 4; i++) {
        int r = row0 + ty * 4 + i;
        int c = o0 + tx * 8;
        float2 a0 = unpack2(acc[i][0]), a1 = unpack2(acc[i][1]);
        float2 a2 = unpack2(acc[i][2]), a3 = unpack2(acc[i][3]);
        float4 v0 = make_float4(a0.x, a0.y, a1.x, a1.y);
        float4 v1 = make_float4(a2.x, a2.y, a3.x, a3.y);
        float* dst = (MODE == 0) ? g_h : C;
        if (MODE == 1) {
            v0.x += bias[c];     v0.y += bias[c + 1];
            v0.z += bias[c + 2]; v0.w += bias[c + 3];
            v1.x += bias[c + 4]; v1.y += bias[c + 5];
            v1.z += bias[c + 6]; v1.w += bias[c + 7];
        }
        *(float4*)&dst[r * OUT_F + c]     = v0;
        *(float4*)&dst[r * OUT_F + c + 4] = v1;
    }
}

// ---------------------------------------------------------------------------
// coe: per (head,n) dot products + precomputed exponentials
// ---------------------------------------------------------------------------
__global__ __launch_bounds__(256) void coe_kernel(
    const float* __restrict__ wi, const float* __restrict__ wj)
{
    int w = threadIdx.x >> 5, lane = threadIdx.x & 31;
    int n = blockIdx.x * 8 + w, h = blockIdx.y;
    float4 hv = *(const float4*)&g_h[n * OUT_F + h * HEAD_F + lane * 4];
    float4 a  = *(const float4*)&wi[h * HEAD_F + lane * 4];
    float4 b  = *(const float4*)&wj[h * HEAD_F + lane * 4];
    float si = hv.x * a.x + hv.y * a.y + hv.z * a.z + hv.w * a.w;
    float sj = hv.x * b.x + hv.y * b.y + hv.z * b.z + hv.w * b.w;
#pragma unroll
    for (int o = 16; o; o >>= 1) {
        si += __shfl_xor_sync(0xffffffffu, si, o);
        sj += __shfl_xor_sync(0xffffffffu, sj, o);
    }
    if (lane == 0) {
        g_ci4[h * N_NODES + n] = make_float4(si, __expf(si), __expf(0.2f * si), 0.f);
        g_cj4[h * N_NODES + n] = make_float4(sj, __expf(sj), __expf(0.2f * sj), 0.f);
    }
}

// ---------------------------------------------------------------------------
// Transposed bitmask: g_maskT[mw*N + n] bit j = graph[mw*32+j][n] > 0
// ---------------------------------------------------------------------------
__global__ __launch_bounds__(256) void maskt_kernel(const int* __restrict__ graph)
{
    int n  = blockIdx.y * 256 + threadIdx.x;
    int mw = blockIdx.x;
    const int* gp = &graph[(mw * 32) * N_NODES + n];
    unsigned w = 0;
#pragma unroll
    for (int j = 0; j < 32; j++)
        w |= (unsigned)(__ldg(&gp[j * N_NODES]) > 0) << j;
    g_maskT[mw * N_NODES + n] = w;
}

// ---------------------------------------------------------------------------
// h -> bf16 transpose: g_hT16[hf][n] = bf16(g_h[n][hf]); coalesced both ways.
// ---------------------------------------------------------------------------
__global__ __launch_bounds__(256) void hT_kernel()
{
    __shared__ float s[32][33];
    const int n0 = blockIdx.x * 32, c0 = blockIdx.y * 32, t = threadIdx.x;
#pragma unroll
    for (int i = 0; i < 4; i++) {
        int idx = i * 256 + t, rr = idx >> 5, cc = idx & 31;
        s[rr][cc] = g_h[(n0 + rr) * OUT_F + c0 + cc];
    }
    __syncthreads();
#pragma unroll
    for (int i = 0; i < 4; i++) {
        int idx = i * 256 + t, cc = idx >> 5, nn = idx & 31;
        *(__nv_bfloat16*)&g_hT16[(c0 + cc) * N_NODES + n0 + nn] =
            __float2bfloat16(s[nn][cc]);
    }
}

// ---------------------------------------------------------------------------
// Attention on mma.sync bf16. CTA = 128 query rows x 1 head, 256 threads.
// Per 32-key tile:
//   phase1: build P[128x32] bf16 (stride-17 words) + stage Ht[128f x 32k]
//           (4 x 64-bit loads/thread from pre-transposed g_hT16)
//   phase2: 8 warps (4m x 2n) each do 2mt x 8nt x 2ks mma.m16n8k16
// Denominator = fp32 sum of the SAME bf16-rounded p (first-order consistent).
// Normalizer cancels vs reference (bounded logits, no max subtraction).
// ---------------------------------------------------------------------------
__global__ __launch_bounds__(256, 2) void attn_kernel(float* __restrict__ out)
{
    __shared__ unsigned P_s[128 * 17];     // row stride 17 words (16 bf16x2 + pad)
    __shared__ unsigned Ht [128 * 17];     // [f][keyword], stride 17
    __shared__ float cjx[2][32], cja[2][32], cjb[2][32];
    __shared__ float sum_s[2][128];

    const int t    = threadIdx.x;
    const int w    = t >> 5;
    const int lane = t & 31;
    const int g    = lane >> 2;            // groupID
    const int tig  = lane & 3;             // thread-in-group
    const int warp_m = (w & 3) * 32;
    const int warp_n = (w >> 2) * 64;
    const int n0   = blockIdx.x * 128;
    const int head = blockIdx.y;

    // P-build mapping
    const int r    = t & 127;
    const int half = t >> 7;
    const float4 ci = g_ci4[head * N_NODES + n0 + r];
    float rsum = 0.f;

    float acc[2][8][4];
#pragma unroll
    for (int mt = 0; mt < 2; mt++)
#pragma unroll
        for (int nt = 0; nt < 8; nt++)
#pragma unroll
            for (int q = 0; q < 4; q++) acc[mt][nt][q] = 0.f;

    // prologue: stage cj for tile 0, prefetch mask word
    if (t < 32) {
        float4 c4 = __ldg(&g_cj4[head * N_NODES + t]);
        cjx[0][t] = c4.x; cja[0][t] = c4.y; cjb[0][t] = c4.z;
    }
    unsigned mcur = __ldg(&g_maskT[n0 + r]);

    for (int tile = 0; tile < N_NODES / 32; ++tile) {
        const int m0  = tile * 32;
        const int buf = tile & 1;
        __syncthreads();   // previous tile's mma done; staged cj visible

        // ---- phase 1a: P tile (this thread: row r, keys half*16..+15) -----
#pragma unroll
        for (int j2 = 0; j2 < 8; j2++) {
            const int k = half * 16 + j2 * 2;
            float s0 = ci.x + cjx[buf][k];
            float pa0 = s0 > 0.f ? ci.y : ci.z;
            float pb0 = s0 > 0.f ? cja[buf][k] : cjb[buf][k];
            float p0 = ((mcur >> k) & 1u) ? pa0 * pb0 : 0.f;
            float s1 = ci.x + cjx[buf][k + 1];
            float pa1 = s1 > 0.f ? ci.y : ci.z;
            float pb1 = s1 > 0.f ? cja[buf][k + 1] : cjb[buf][k + 1];
            float p1 = ((mcur >> (k + 1)) & 1u) ? pa1 * pb1 : 0.f;
            unsigned pw = pack_bf16x2(p0, p1);
            P_s[r * 17 + half * 8 + j2] = pw;
            float2 pr = unpack_bf16x2(pw);     // rounded values -> denominator
            rsum += pr.x + pr.y;
        }

        // ---- phase 1b: stage Ht (128f x 16 words = 1024 u64, 4 iters) -----
#pragma unroll
        for (int i = 0; i < 4; i++) {
            int idx = i * 256 + t;
            int f = idx >> 3, pr8 = idx & 7;
            uint2 v = __ldg(&((const uint2*)g_hT16)[(head * 128 + f) * (N_NODES / 4) + (m0 >> 2) + pr8]);
            Ht[f * 17 + 2 * pr8]     = v.x;
            Ht[f * 17 + 2 * pr8 + 1] = v.y;
        }
        // prefetch next tile's cj + mask
        if (t < 32 && tile + 1 < N_NODES / 32) {
            float4 c4 = __ldg(&g_cj4[head * N_NODES + (tile + 1) * 32 + t]);
            cjx[buf ^ 1][t] = c4.x; cja[buf ^ 1][t] = c4.y; cjb[buf ^ 1][t] = c4.z;
        }
        unsigned mnext = (tile + 1 < N_NODES / 32)
                         ? __ldg(&g_maskT[(tile + 1) * N_NODES + n0 + r]) : 0u;

        __syncthreads();   // P_s + Ht visible

        // ---- phase 2: mma ------------------------------------------------
#pragma unroll
        for (int ks = 0; ks < 2; ks++) {
            unsigned afr[2][4];
#pragma unroll
            for (int mt = 0; mt < 2; mt++) {
                int base = (warp_m + mt * 16 + g) * 17 + ks * 8 + tig;
                afr[mt][0] = P_s[base];
                afr[mt][1] = P_s[base + 8 * 17];
                afr[mt][2] = P_s[base + 4];
                afr[mt][3] = P_s[base + 8 * 17 + 4];
            }
            int bb = (warp_n + g) * 17 + ks * 8 + tig;
#pragma unroll
            for (int nt = 0; nt < 8; nt++) {
                unsigned b0 = Ht[bb + nt * 8 * 17];
                unsigned b1 = Ht[bb + nt * 8 * 17 + 4];
                mma_bf16(acc[0][nt], afr[0], b0, b1);
                mma_bf16(acc[1][nt], afr[1], b0, b1);
            }
        }
        mcur = mnext;
    }

    sum_s[half][r] = rsum;
    __syncthreads();

    // ---- epilogue: out += D * (1/rowsum); residual already in out ---------
#pragma unroll
    for (int mt = 0; mt < 2; mt++) {
        const int rl0 = warp_m + mt * 16 + g;
        const int rl1 = rl0 + 8;
        const float inv0 = 1.f / (sum_s[0][rl0] + sum_s[1][rl0]);
        const float inv1 = 1.f / (sum_s[0][rl1] + sum_s[1][rl1]);
#pragma unroll
        for (int nt = 0; nt < 8; nt++) {
            const int col = head * HEAD_F + warp_n + nt * 8 + 2 * tig;
            float2* q0 = (float2*)&out[(n0 + rl0) * OUT_F + col];
            float2 v = *q0;
            v.x += acc[mt][nt][0] * inv0;
            v.y += acc[mt][nt][1] * inv0;
            *q0 = v;
            float2* q1 = (float2*)&out[(n0 + rl1) * OUT_F + col];
            v = *q1;
            v.x += acc[mt][nt][2] * inv1;
            v.y += acc[mt][nt][3] * inv1;
            *q1 = v;
        }
    }
}

// ---------------------------------------------------------------------------
extern "C" void kernel_launch(void* const* d_in, const int* in_sizes, int n_in,
                              void* d_out, int out_size)
{
    const float* x     = (const float*)d_in[0];
    const int*   graph = (const int*)  d_in[1];
    const float* W     = (const float*)d_in[2];
    const float* w_i   = (const float*)d_in[3];
    const float* w_j   = (const float*)d_in[4];
    const float* W_r   = (const float*)d_in[5];
    const float* bias  = (const float*)d_in[6];
    float* out = (float*)d_out;

    maskt_kernel<<<dim3(N_NODES / 32, N_NODES / 256), 256>>>(graph);
    gemm_kernel<0><<<dim3(N_NODES / 64, OUT_F / 128), 256>>>(x, W, nullptr, nullptr);
    gemm_kernel<1><<<dim3(N_NODES / 64, OUT_F / 128), 256>>>(x, W_r, bias, out);
    hT_kernel<<<dim3(N_NODES / 32, OUT_F / 32), 256>>>();
    coe_kernel<<<dim3(N_NODES / 8, HEADS), 256>>>(w_i, w_j);
    attn_kernel<<<dim3(N_NODES / 128, HEADS), 256>>>(out);
}

// round 7
// speedup vs baseline: 3.5612x; 1.1639x over previous
#include <cuda_runtime.h>
#include <cuda_bf16.h>

#define N_NODES 4096
#define IN_F    512
#define OUT_F   1024
#define HEADS   8
#define HEAD_F  128

// Scratch (device globals — no allocation allowed)
__device__ float          g_h    [N_NODES * OUT_F];            // h [n][head*128+f]
__device__ float4         g_ci4  [HEADS * N_NODES];            // (ci, e^ci, e^{0.2ci}, -)
__device__ float4         g_cj4  [HEADS * N_NODES];            // (cj, e^cj, e^{0.2cj}, -)
__device__ unsigned short g_hT16 [OUT_F * N_NODES];            // bf16 h^T [head*128+f][n]
__device__ unsigned int   g_maskT[(N_NODES / 32) * N_NODES];   // word [mw][n], bit j = graph[mw*32+j][n]>0

// ---- helpers --------------------------------------------------------------
__device__ __forceinline__ unsigned smem_u32(const void* p) {
    unsigned a;
    asm("{ .reg .u64 t; cvta.to.shared.u64 t, %1; cvt.u32.u64 %0, t; }" : "=r"(a) : "l"(p));
    return a;
}
__device__ __forceinline__ void ffma2(unsigned long long& d, unsigned long long a,
                                      unsigned long long b) {
    asm("fma.rn.f32x2 %0, %1, %2, %0;" : "+l"(d) : "l"(a), "l"(b));
}
__device__ __forceinline__ unsigned long long pack2(float x) {
    unsigned long long r;
    asm("mov.b64 %0, {%1, %1};" : "=l"(r) : "f"(x));
    return r;
}
__device__ __forceinline__ float2 unpack2(unsigned long long u) {
    float2 f;
    asm("mov.b64 {%0, %1}, %2;" : "=f"(f.x), "=f"(f.y) : "l"(u));
    return f;
}
__device__ __forceinline__ void mma_bf16(float* d, const unsigned* a,
                                         unsigned b0, unsigned b1) {
    asm volatile(
        "mma.sync.aligned.m16n8k16.row.col.f32.bf16.bf16.f32 "
        "{%0,%1,%2,%3}, {%4,%5,%6,%7}, {%8,%9}, {%0,%1,%2,%3};"
        : "+f"(d[0]), "+f"(d[1]), "+f"(d[2]), "+f"(d[3])
        : "r"(a[0]), "r"(a[1]), "r"(a[2]), "r"(a[3]), "r"(b0), "r"(b1));
}
__device__ __forceinline__ void ldmatrix_x4(unsigned* d, unsigned addr) {
    asm volatile("ldmatrix.sync.aligned.m8n8.x4.shared.b16 {%0,%1,%2,%3}, [%4];"
        : "=r"(d[0]), "=r"(d[1]), "=r"(d[2]), "=r"(d[3]) : "r"(addr));
}
__device__ __forceinline__ unsigned pack_bf16x2(float lo, float hi) {
    unsigned u;
    asm("cvt.rn.bf16x2.f32 %0, %1, %2;" : "=r"(u) : "f"(hi), "f"(lo));
    return u;
}
__device__ __forceinline__ float2 unpack_bf16x2(unsigned u) {
    float2 r;
    r.x = __uint_as_float(u << 16);
    r.y = __uint_as_float(u & 0xffff0000u);
    return r;
}

// ---------------------------------------------------------------------------
// GEMM: C[4096,1024] = A[4096,512] @ B  (MODE 0 -> g_h, MODE 1 -> out +bias)
// BM=128, BN=128, BK=16; 256 threads, 8x8 per thread, FFMA2; FMA-pipe bound.
// ---------------------------------------------------------------------------
template <int MODE>
__global__ __launch_bounds__(256) void gemm_kernel(
    const float* __restrict__ A, const float* __restrict__ B,
    const float* __restrict__ bias, float* __restrict__ C)
{
    constexpr int BM = 128, BN = 128, BK = 16;
    __shared__ float As[BM][BK + 4];      // row-major, stride 20 words
    __shared__ float Bs[BK][BN];

    const int t  = threadIdx.x;
    const int tx = t & 15, ty = t >> 4;
    const int row0 = blockIdx.x * BM;
    const int o0   = blockIdx.y * BN;

    unsigned long long acc[8][4];
#pragma unroll
    for (int i = 0; i < 8; i++)
#pragma unroll
        for (int j = 0; j < 4; j++) acc[i][j] = 0ull;

    for (int k0 = 0; k0 < IN_F; k0 += BK) {
        // A tile: 128 rows x 16 k = 512 float4
#pragma unroll
        for (int i = 0; i < 2; i++) {
            int idx = t + i * 256;
            int r = idx >> 2, kq = (idx & 3) * 4;
            float4 v = *(const float4*)&A[(row0 + r) * IN_F + k0 + kq];
            *(float4*)&As[r][kq] = v;
        }
        // B tile: 16 k x 128 cols = 512 float4
#pragma unroll
        for (int i = 0; i < 2; i++) {
            int idx = t + i * 256;
            int k = idx >> 5, c4 = (idx & 31) * 4;
            float4 v;
            if (MODE == 0)
                v = *(const float4*)&B[blockIdx.y * (IN_F * HEAD_F) + (k0 + k) * HEAD_F + c4];
            else
                v = *(const float4*)&B[(k0 + k) * OUT_F + o0 + c4];
            *(float4*)&Bs[k][c4] = v;
        }
        __syncthreads();

#pragma unroll
        for (int k = 0; k < BK; k++) {
            ulonglong2 b0 = *(const ulonglong2*)&Bs[k][tx * 8];
            ulonglong2 b1 = *(const ulonglong2*)&Bs[k][tx * 8 + 4];
#pragma unroll
            for (int i = 0; i < 8; i++) {
                unsigned long long av = pack2(As[ty * 8 + i][k]);
                ffma2(acc[i][0], av, b0.x);
                ffma2(acc[i][1], av, b0.y);
                ffma2(acc[i][2], av, b1.x);
                ffma2(acc[i][3], av, b1.y);
            }
        }
        __syncthreads();
    }

#pragma unroll
    for (int i = 0; i < 8; i++) {
        int r = row0 + ty * 8 + i;
        int c = o0 + tx * 8;
        float2 a0 = unpack2(acc[i][0]), a1 = unpack2(acc[i][1]);
        float2 a2 = unpack2(acc[i][2]), a3 = unpack2(acc[i][3]);
        float4 v0 = make_float4(a0.x, a0.y, a1.x, a1.y);
        float4 v1 = make_float4(a2.x, a2.y, a3.x, a3.y);
        float* dst = (MODE == 0) ? g_h : C;
        if (MODE == 1) {
            v0.x += bias[c];     v0.y += bias[c + 1];
            v0.z += bias[c + 2]; v0.w += bias[c + 3];
            v1.x += bias[c + 4]; v1.y += bias[c + 5];
            v1.z += bias[c + 6]; v1.w += bias[c + 7];
        }
        *(float4*)&dst[r * OUT_F + c]     = v0;
        *(float4*)&dst[r * OUT_F + c + 4] = v1;
    }
}

// ---------------------------------------------------------------------------
// coe: per (head,n) dot products + precomputed exponentials
// ---------------------------------------------------------------------------
__global__ __launch_bounds__(256) void coe_kernel(
    const float* __restrict__ wi, const float* __restrict__ wj)
{
    int w = threadIdx.x >> 5, lane = threadIdx.x & 31;
    int n = blockIdx.x * 8 + w, h = blockIdx.y;
    float4 hv = *(const float4*)&g_h[n * OUT_F + h * HEAD_F + lane * 4];
    float4 a  = *(const float4*)&wi[h * HEAD_F + lane * 4];
    float4 b  = *(const float4*)&wj[h * HEAD_F + lane * 4];
    float si = hv.x * a.x + hv.y * a.y + hv.z * a.z + hv.w * a.w;
    float sj = hv.x * b.x + hv.y * b.y + hv.z * b.z + hv.w * b.w;
#pragma unroll
    for (int o = 16; o; o >>= 1) {
        si += __shfl_xor_sync(0xffffffffu, si, o);
        sj += __shfl_xor_sync(0xffffffffu, sj, o);
    }
    if (lane == 0) {
        g_ci4[h * N_NODES + n] = make_float4(si, __expf(si), __expf(0.2f * si), 0.f);
        g_cj4[h * N_NODES + n] = make_float4(sj, __expf(sj), __expf(0.2f * sj), 0.f);
    }
}

// ---------------------------------------------------------------------------
// Transposed bitmask: g_maskT[mw*N + n] bit j = graph[mw*32+j][n] > 0
// ---------------------------------------------------------------------------
__global__ __launch_bounds__(256) void maskt_kernel(const int* __restrict__ graph)
{
    int n  = blockIdx.y * 256 + threadIdx.x;
    int mw = blockIdx.x;
    const int* gp = &graph[(mw * 32) * N_NODES + n];
    unsigned w = 0;
#pragma unroll
    for (int j = 0; j < 32; j++)
        w |= (unsigned)(__ldg(&gp[j * N_NODES]) > 0) << j;
    g_maskT[mw * N_NODES + n] = w;
}

// ---------------------------------------------------------------------------
// h -> bf16 transpose: g_hT16[hf][n] = bf16(g_h[n][hf])
// ---------------------------------------------------------------------------
__global__ __launch_bounds__(256) void hT_kernel()
{
    __shared__ float s[32][33];
    const int n0 = blockIdx.x * 32, c0 = blockIdx.y * 32, t = threadIdx.x;
#pragma unroll
    for (int i = 0; i < 4; i++) {
        int idx = i * 256 + t, rr = idx >> 5, cc = idx & 31;
        s[rr][cc] = g_h[(n0 + rr) * OUT_F + c0 + cc];
    }
    __syncthreads();
#pragma unroll
    for (int i = 0; i < 4; i++) {
        int idx = i * 256 + t, cc = idx >> 5, nn = idx & 31;
        *(__nv_bfloat16*)&g_hT16[(c0 + cc) * N_NODES + n0 + nn] =
            __float2bfloat16(s[nn][cc]);
    }
}

// ---------------------------------------------------------------------------
// Attention on mma.sync bf16 + ldmatrix. CTA = 128 rows x 1 head, 256 thr.
// SMEM rows stride 20 words (16B-aligned rows, conflict-free ldmatrix).
// Per 32-key tile: build P bf16 (2 uint4 stores) + stage Ht (uint4), then
// 8 warps (4m x 2n): 12 ldmatrix.x4 + 32 mma.m16n8k16.
// ---------------------------------------------------------------------------
__global__ __launch_bounds__(256, 2) void attn_kernel(float* __restrict__ out)
{
    constexpr int PST = 20;                // row stride in words
    __shared__ unsigned P_s[128 * PST];
    __shared__ unsigned Ht [128 * PST];
    __shared__ float cjx[2][32], cja[2][32], cjb[2][32];
    __shared__ float sum_s[2][128];

    const int t    = threadIdx.x;
    const int w    = t >> 5;
    const int lane = t & 31;
    const int g    = lane >> 2;
    const int tig  = lane & 3;
    const int warp_m = (w & 3) * 32;
    const int warp_n = (w >> 2) * 64;
    const int n0   = blockIdx.x * 128;
    const int head = blockIdx.y;

    // ldmatrix lane addresses (loop-invariant)
    const unsigned Pb = smem_u32(P_s), Hb = smem_u32(Ht);
    unsigned aaddr[2][2], baddr[2][2][2];
    {
        int arow = warp_m + (lane & 15);
        int ak   = (lane >> 4) << 2;               // +4 words for k-hi quads
#pragma unroll
        for (int mt = 0; mt < 2; mt++)
#pragma unroll
            for (int ks = 0; ks < 2; ks++)
                aaddr[mt][ks] = Pb + 4u * ((arow + mt * 16) * PST + ks * 8 + ak);
        int brow = warp_n + (lane >> 3) * 8 + (lane & 7);
#pragma unroll
        for (int ks = 0; ks < 2; ks++)
#pragma unroll
            for (int hf = 0; hf < 2; hf++)
#pragma unroll
                for (int ng = 0; ng < 2; ng++)
                    baddr[ks][hf][ng] = Hb + 4u * ((brow + ng * 32) * PST + ks * 8 + hf * 4);
    }

    // P-build mapping
    const int r    = t & 127;
    const int half = t >> 7;
    const float4 ci = g_ci4[head * N_NODES + n0 + r];
    float rsum = 0.f;

    float acc[2][8][4];
#pragma unroll
    for (int mt = 0; mt < 2; mt++)
#pragma unroll
        for (int nt = 0; nt < 8; nt++)
#pragma unroll
            for (int q = 0; q < 4; q++) acc[mt][nt][q] = 0.f;

    if (t < 32) {
        float4 c4 = __ldg(&g_cj4[head * N_NODES + t]);
        cjx[0][t] = c4.x; cja[0][t] = c4.y; cjb[0][t] = c4.z;
    }
    unsigned mcur = __ldg(&g_maskT[n0 + r]);

    for (int tile = 0; tile < N_NODES / 32; ++tile) {
        const int m0  = tile * 32;
        const int buf = tile & 1;
        __syncthreads();   // prev mma done; staged cj visible

        // ---- P tile (row r, keys half*16..+15) ----------------------------
        unsigned pw[8];
#pragma unroll
        for (int j2 = 0; j2 < 8; j2++) {
            const int k = half * 16 + j2 * 2;
            float s0 = ci.x + cjx[buf][k];
            float pa0 = s0 > 0.f ? ci.y : ci.z;
            float pb0 = s0 > 0.f ? cja[buf][k] : cjb[buf][k];
            float p0 = ((mcur >> k) & 1u) ? pa0 * pb0 : 0.f;
            float s1 = ci.x + cjx[buf][k + 1];
            float pa1 = s1 > 0.f ? ci.y : ci.z;
            float pb1 = s1 > 0.f ? cja[buf][k + 1] : cjb[buf][k + 1];
            float p1 = ((mcur >> (k + 1)) & 1u) ? pa1 * pb1 : 0.f;
            pw[j2] = pack_bf16x2(p0, p1);
            float2 pr = unpack_bf16x2(pw[j2]);
            rsum += pr.x + pr.y;
        }
        *(uint4*)&P_s[r * PST + half * 8]     = make_uint4(pw[0], pw[1], pw[2], pw[3]);
        *(uint4*)&P_s[r * PST + half * 8 + 4] = make_uint4(pw[4], pw[5], pw[6], pw[7]);

        // ---- Ht tile: 128 f x 4 uint4 = 512 uint4, 2 iters ---------------
#pragma unroll
        for (int i = 0; i < 2; i++) {
            int idx = i * 256 + t;
            int f = idx >> 2, q = idx & 3;
            uint4 v = __ldg(&((const uint4*)g_hT16)[(head * 128 + f) * (N_NODES / 8) + (m0 >> 3) + q]);
            *(uint4*)&Ht[f * PST + q * 4] = v;
        }
        if (t < 32 && tile + 1 < N_NODES / 32) {
            float4 c4 = __ldg(&g_cj4[head * N_NODES + (tile + 1) * 32 + t]);
            cjx[buf ^ 1][t] = c4.x; cja[buf ^ 1][t] = c4.y; cjb[buf ^ 1][t] = c4.z;
        }
        unsigned mnext = (tile + 1 < N_NODES / 32)
                         ? __ldg(&g_maskT[(tile + 1) * N_NODES + n0 + r]) : 0u;

        __syncthreads();

        // ---- mma: ldmatrix fragments + 32 mma -----------------------------
#pragma unroll
        for (int ks = 0; ks < 2; ks++) {
            unsigned af0[4], af1[4];
            ldmatrix_x4(af0, aaddr[0][ks]);
            ldmatrix_x4(af1, aaddr[1][ks]);
            unsigned b0a[4], b0b[4], b1a[4], b1b[4];
            ldmatrix_x4(b0a, baddr[ks][0][0]);   // b0, nt 0-3
            ldmatrix_x4(b0b, baddr[ks][0][1]);   // b0, nt 4-7
            ldmatrix_x4(b1a, baddr[ks][1][0]);   // b1, nt 0-3
            ldmatrix_x4(b1b, baddr[ks][1][1]);   // b1, nt 4-7
#pragma unroll
            for (int nt = 0; nt < 8; nt++) {
                unsigned b0 = (nt < 4) ? b0a[nt] : b0b[nt - 4];
                unsigned b1 = (nt < 4) ? b1a[nt] : b1b[nt - 4];
                mma_bf16(acc[0][nt], af0, b0, b1);
                mma_bf16(acc[1][nt], af1, b0, b1);
            }
        }
        mcur = mnext;
    }

    sum_s[half][r] = rsum;
    __syncthreads();

    // ---- epilogue: out += D * (1/rowsum); residual already in out ---------
#pragma unroll
    for (int mt = 0; mt < 2; mt++) {
        const int rl0 = warp_m + mt * 16 + g;
        const int rl1 = rl0 + 8;
        const float inv0 = 1.f / (sum_s[0][rl0] + sum_s[1][rl0]);
        const float inv1 = 1.f / (sum_s[0][rl1] + sum_s[1][rl1]);
#pragma unroll
        for (int nt = 0; nt < 8; nt++) {
            const int col = head * HEAD_F + warp_n + nt * 8 + 2 * tig;
            float2* q0 = (float2*)&out[(n0 + rl0) * OUT_F + col];
            float2 v = *q0;
            v.x += acc[mt][nt][0] * inv0;
            v.y += acc[mt][nt][1] * inv0;
            *q0 = v;
            float2* q1 = (float2*)&out[(n0 + rl1) * OUT_F + col];
            v = *q1;
            v.x += acc[mt][nt][2] * inv1;
            v.y += acc[mt][nt][3] * inv1;
            *q1 = v;
        }
    }
}

// ---------------------------------------------------------------------------
extern "C" void kernel_launch(void* const* d_in, const int* in_sizes, int n_in,
                              void* d_out, int out_size)
{
    const float* x     = (const float*)d_in[0];
    const int*   graph = (const int*)  d_in[1];
    const float* W     = (const float*)d_in[2];
    const float* w_i   = (const float*)d_in[3];
    const float* w_j   = (const float*)d_in[4];
    const float* W_r   = (const float*)d_in[5];
    const float* bias  = (const float*)d_in[6];
    float* out = (float*)d_out;

    maskt_kernel<<<dim3(N_NODES / 32, N_NODES / 256), 256>>>(graph);
    gemm_kernel<0><<<dim3(N_NODES / 128, OUT_F / 128), 256>>>(x, W, nullptr, nullptr);
    gemm_kernel<1><<<dim3(N_NODES / 128, OUT_F / 128), 256>>>(x, W_r, bias, out);
    hT_kernel<<<dim3(N_NODES / 32, OUT_F / 32), 256>>>();
    coe_kernel<<<dim3(N_NODES / 8, HEADS), 256>>>(w_i, w_j);
    attn_kernel<<<dim3(N_NODES / 128, HEADS), 256>>>(out);
}

// round 8
// speedup vs baseline: 3.6893x; 1.0360x over previous
#include <cuda_runtime.h>
#include <cuda_bf16.h>

#define N_NODES 4096
#define IN_F    512
#define OUT_F   1024
#define HEADS   8
#define HEAD_F  128

// Scratch (device globals — no allocation allowed)
__device__ float          g_h    [N_NODES * OUT_F];            // h [n][head*128+f]
__device__ float4         g_ci4  [HEADS * N_NODES];            // (ci, e^ci, e^{0.2ci}, -)
__device__ float4         g_cj4  [HEADS * N_NODES];            // (cj, e^cj, e^{0.2cj}, -)
__device__ unsigned short g_hT16 [OUT_F * N_NODES];            // bf16 h^T [head*128+f][n]
__device__ unsigned int   g_maskT[(N_NODES / 32) * N_NODES];   // word [mw][n], bit j = graph[mw*32+j][n]>0

// ---- helpers --------------------------------------------------------------
__device__ __forceinline__ unsigned smem_u32(const void* p) {
    unsigned a;
    asm("{ .reg .u64 t; cvta.to.shared.u64 t, %1; cvt.u32.u64 %0, t; }" : "=r"(a) : "l"(p));
    return a;
}
__device__ __forceinline__ void ffma2(unsigned long long& d, unsigned long long a,
                                      unsigned long long b) {
    asm("fma.rn.f32x2 %0, %1, %2, %0;" : "+l"(d) : "l"(a), "l"(b));
}
__device__ __forceinline__ unsigned long long pack2(float x) {
    unsigned long long r;
    asm("mov.b64 %0, {%1, %1};" : "=l"(r) : "f"(x));
    return r;
}
__device__ __forceinline__ float2 unpack2(unsigned long long u) {
    float2 f;
    asm("mov.b64 {%0, %1}, %2;" : "=f"(f.x), "=f"(f.y) : "l"(u));
    return f;
}
__device__ __forceinline__ void mma_bf16(float* d, const unsigned* a,
                                         unsigned b0, unsigned b1) {
    asm volatile(
        "mma.sync.aligned.m16n8k16.row.col.f32.bf16.bf16.f32 "
        "{%0,%1,%2,%3}, {%4,%5,%6,%7}, {%8,%9}, {%0,%1,%2,%3};"
        : "+f"(d[0]), "+f"(d[1]), "+f"(d[2]), "+f"(d[3])
        : "r"(a[0]), "r"(a[1]), "r"(a[2]), "r"(a[3]), "r"(b0), "r"(b1));
}
__device__ __forceinline__ void ldmatrix_x4(unsigned* d, unsigned addr) {
    asm volatile("ldmatrix.sync.aligned.m8n8.x4.shared.b16 {%0,%1,%2,%3}, [%4];"
        : "=r"(d[0]), "=r"(d[1]), "=r"(d[2]), "=r"(d[3]) : "r"(addr));
}
__device__ __forceinline__ unsigned pack_bf16x2(float lo, float hi) {
    unsigned u;
    asm("cvt.rn.bf16x2.f32 %0, %1, %2;" : "=r"(u) : "f"(hi), "f"(lo));
    return u;
}
__device__ __forceinline__ float2 unpack_bf16x2(unsigned u) {
    float2 r;
    r.x = __uint_as_float(u << 16);
    r.y = __uint_as_float(u & 0xffff0000u);
    return r;
}

// ---------------------------------------------------------------------------
// GEMM: g_h = x[4096,512] @ W (head-blocked) ; BM=128,BN=128,BK=16, FFMA2.
// ---------------------------------------------------------------------------
__global__ __launch_bounds__(256) void gemm_kernel(
    const float* __restrict__ A, const float* __restrict__ B)
{
    constexpr int BK = 16;
    __shared__ float As[128][BK + 4];
    __shared__ float Bs[BK][128];

    const int t  = threadIdx.x;
    const int tx = t & 15, ty = t >> 4;
    const int row0 = blockIdx.x * 128;

    unsigned long long acc[8][4];
#pragma unroll
    for (int i = 0; i < 8; i++)
#pragma unroll
        for (int j = 0; j < 4; j++) acc[i][j] = 0ull;

    for (int k0 = 0; k0 < IN_F; k0 += BK) {
#pragma unroll
        for (int i = 0; i < 2; i++) {
            int idx = t + i * 256;
            int r = idx >> 2, kq = (idx & 3) * 4;
            float4 v = *(const float4*)&A[(row0 + r) * IN_F + k0 + kq];
            *(float4*)&As[r][kq] = v;
        }
#pragma unroll
        for (int i = 0; i < 2; i++) {
            int idx = t + i * 256;
            int k = idx >> 5, c4 = (idx & 31) * 4;
            float4 v = *(const float4*)&B[blockIdx.y * (IN_F * HEAD_F) + (k0 + k) * HEAD_F + c4];
            *(float4*)&Bs[k][c4] = v;
        }
        __syncthreads();

#pragma unroll
        for (int k = 0; k < BK; k++) {
            ulonglong2 b0 = *(const ulonglong2*)&Bs[k][tx * 8];
            ulonglong2 b1 = *(const ulonglong2*)&Bs[k][tx * 8 + 4];
#pragma unroll
            for (int i = 0; i < 8; i++) {
                unsigned long long av = pack2(As[ty * 8 + i][k]);
                ffma2(acc[i][0], av, b0.x);
                ffma2(acc[i][1], av, b0.y);
                ffma2(acc[i][2], av, b1.x);
                ffma2(acc[i][3], av, b1.y);
            }
        }
        __syncthreads();
    }

#pragma unroll
    for (int i = 0; i < 8; i++) {
        int r = row0 + ty * 8 + i;
        int c = blockIdx.y * 128 + tx * 8;
        float2 a0 = unpack2(acc[i][0]), a1 = unpack2(acc[i][1]);
        float2 a2 = unpack2(acc[i][2]), a3 = unpack2(acc[i][3]);
        *(float4*)&g_h[r * OUT_F + c]     = make_float4(a0.x, a0.y, a1.x, a1.y);
        *(float4*)&g_h[r * OUT_F + c + 4] = make_float4(a2.x, a2.y, a3.x, a3.y);
    }
}

// ---------------------------------------------------------------------------
// coe: per (head,n) dot products + precomputed exponentials
// ---------------------------------------------------------------------------
__global__ __launch_bounds__(256) void coe_kernel(
    const float* __restrict__ wi, const float* __restrict__ wj)
{
    int w = threadIdx.x >> 5, lane = threadIdx.x & 31;
    int n = blockIdx.x * 8 + w, h = blockIdx.y;
    float4 hv = *(const float4*)&g_h[n * OUT_F + h * HEAD_F + lane * 4];
    float4 a  = *(const float4*)&wi[h * HEAD_F + lane * 4];
    float4 b  = *(const float4*)&wj[h * HEAD_F + lane * 4];
    float si = hv.x * a.x + hv.y * a.y + hv.z * a.z + hv.w * a.w;
    float sj = hv.x * b.x + hv.y * b.y + hv.z * b.z + hv.w * b.w;
#pragma unroll
    for (int o = 16; o; o >>= 1) {
        si += __shfl_xor_sync(0xffffffffu, si, o);
        sj += __shfl_xor_sync(0xffffffffu, sj, o);
    }
    if (lane == 0) {
        g_ci4[h * N_NODES + n] = make_float4(si, __expf(si), __expf(0.2f * si), 0.f);
        g_cj4[h * N_NODES + n] = make_float4(sj, __expf(sj), __expf(0.2f * sj), 0.f);
    }
}

// ---------------------------------------------------------------------------
// Transposed bitmask: g_maskT[mw*N + n] bit j = graph[mw*32+j][n] > 0
// ---------------------------------------------------------------------------
__global__ __launch_bounds__(256) void maskt_kernel(const int* __restrict__ graph)
{
    int n  = blockIdx.y * 256 + threadIdx.x;
    int mw = blockIdx.x;
    const int* gp = &graph[(mw * 32) * N_NODES + n];
    unsigned w = 0;
#pragma unroll
    for (int j = 0; j < 32; j++)
        w |= (unsigned)(__ldg(&gp[j * N_NODES]) > 0) << j;
    g_maskT[mw * N_NODES + n] = w;
}

// ---------------------------------------------------------------------------
// h -> bf16 transpose: g_hT16[hf][n] = bf16(g_h[n][hf])
// ---------------------------------------------------------------------------
__global__ __launch_bounds__(256) void hT_kernel()
{
    __shared__ float s[32][33];
    const int n0 = blockIdx.x * 32, c0 = blockIdx.y * 32, t = threadIdx.x;
#pragma unroll
    for (int i = 0; i < 4; i++) {
        int idx = i * 256 + t, rr = idx >> 5, cc = idx & 31;
        s[rr][cc] = g_h[(n0 + rr) * OUT_F + c0 + cc];
    }
    __syncthreads();
#pragma unroll
    for (int i = 0; i < 4; i++) {
        int idx = i * 256 + t, cc = idx >> 5, nn = idx & 31;
        *(__nv_bfloat16*)&g_hT16[(c0 + cc) * N_NODES + n0 + nn] =
            __float2bfloat16(s[nn][cc]);
    }
}

// ---------------------------------------------------------------------------
// Attention (mma.sync bf16 + ldmatrix) with FUSED residual GEMM + bias.
// CTA = 128 rows x 1 head. Main loop: tensor-bound P@H. Epilogue:
//   (1) out = att*inv (pure stores), (2) out += x@W_r_head + bias (FFMA2,
//   reusing P_s/Ht smem as GEMM tiles) — fma work overlaps other CTA's mma.
// ---------------------------------------------------------------------------
__global__ __launch_bounds__(256, 2) void attn_kernel(
    const float* __restrict__ x, const float* __restrict__ W_r,
    const float* __restrict__ bias, float* __restrict__ out)
{
    constexpr int PST = 20;                // row stride in words
    __shared__ unsigned P_s[128 * PST];    // also reused as As[128][20] (fp32)
    __shared__ unsigned Ht [128 * PST];    // also reused as Bs[16][128] (fp32)
    __shared__ float cjx[2][32], cja[2][32], cjb[2][32];
    __shared__ float sum_s[2][128];

    const int t    = threadIdx.x;
    const int w    = t >> 5;
    const int lane = t & 31;
    const int g    = lane >> 2;
    const int tig  = lane & 3;
    const int warp_m = (w & 3) * 32;
    const int warp_n = (w >> 2) * 64;
    const int n0   = blockIdx.x * 128;
    const int head = blockIdx.y;

    // ldmatrix lane addresses (loop-invariant)
    const unsigned Pb = smem_u32(P_s), Hb = smem_u32(Ht);
    unsigned aaddr[2][2], baddr[2][2][2];
    {
        int arow = warp_m + (lane & 15);
        int ak   = (lane >> 4) << 2;
#pragma unroll
        for (int mt = 0; mt < 2; mt++)
#pragma unroll
            for (int ks = 0; ks < 2; ks++)
                aaddr[mt][ks] = Pb + 4u * ((arow + mt * 16) * PST + ks * 8 + ak);
        int brow = warp_n + (lane >> 3) * 8 + (lane & 7);
#pragma unroll
        for (int ks = 0; ks < 2; ks++)
#pragma unroll
            for (int hf = 0; hf < 2; hf++)
#pragma unroll
                for (int ng = 0; ng < 2; ng++)
                    baddr[ks][hf][ng] = Hb + 4u * ((brow + ng * 32) * PST + ks * 8 + hf * 4);
    }

    const int r    = t & 127;
    const int half = t >> 7;
    const float4 ci = g_ci4[head * N_NODES + n0 + r];
    float rsum = 0.f;

    float acc[2][8][4];
#pragma unroll
    for (int mt = 0; mt < 2; mt++)
#pragma unroll
        for (int nt = 0; nt < 8; nt++)
#pragma unroll
            for (int q = 0; q < 4; q++) acc[mt][nt][q] = 0.f;

    if (t < 32) {
        float4 c4 = __ldg(&g_cj4[head * N_NODES + t]);
        cjx[0][t] = c4.x; cja[0][t] = c4.y; cjb[0][t] = c4.z;
    }
    unsigned mcur = __ldg(&g_maskT[n0 + r]);

    const int hTf = t >> 2, hTq = t & 3;   // Ht staging mapping (2 iters of 256)

    for (int tile = 0; tile < N_NODES / 32; ++tile) {
        const int m0  = tile * 32;
        const int buf = tile & 1;

        // ---- hoisted global loads (latency overlapped with P build) -------
        uint4 hv0 = __ldg(&((const uint4*)g_hT16)[(head * 128 + hTf) * (N_NODES / 8) + (m0 >> 3) + hTq]);
        uint4 hv1 = __ldg(&((const uint4*)g_hT16)[(head * 128 + hTf + 64) * (N_NODES / 8) + (m0 >> 3) + hTq]);
        float4 cjn = make_float4(0.f, 0.f, 0.f, 0.f);
        if (t < 32 && tile + 1 < N_NODES / 32)
            cjn = __ldg(&g_cj4[head * N_NODES + (tile + 1) * 32 + t]);
        unsigned mnext = (tile + 1 < N_NODES / 32)
                         ? __ldg(&g_maskT[(tile + 1) * N_NODES + n0 + r]) : 0u;

        __syncthreads();   // prev mma done; staged cj visible

        // ---- P tile (row r, keys half*16..+15) ----------------------------
        unsigned pw[8];
#pragma unroll
        for (int j2 = 0; j2 < 8; j2++) {
            const int k = half * 16 + j2 * 2;
            float s0 = ci.x + cjx[buf][k];
            float pa0 = s0 > 0.f ? ci.y : ci.z;
            float pb0 = s0 > 0.f ? cja[buf][k] : cjb[buf][k];
            float p0 = ((mcur >> k) & 1u) ? pa0 * pb0 : 0.f;
            float s1 = ci.x + cjx[buf][k + 1];
            float pa1 = s1 > 0.f ? ci.y : ci.z;
            float pb1 = s1 > 0.f ? cja[buf][k + 1] : cjb[buf][k + 1];
            float p1 = ((mcur >> (k + 1)) & 1u) ? pa1 * pb1 : 0.f;
            pw[j2] = pack_bf16x2(p0, p1);
            float2 pr = unpack_bf16x2(pw[j2]);
            rsum += pr.x + pr.y;
        }
        *(uint4*)&P_s[r * PST + half * 8]     = make_uint4(pw[0], pw[1], pw[2], pw[3]);
        *(uint4*)&P_s[r * PST + half * 8 + 4] = make_uint4(pw[4], pw[5], pw[6], pw[7]);

        // ---- Ht tile stores ----------------------------------------------
        *(uint4*)&Ht[hTf * PST + hTq * 4]        = hv0;
        *(uint4*)&Ht[(hTf + 64) * PST + hTq * 4] = hv1;
        if (t < 32 && tile + 1 < N_NODES / 32) {
            cjx[buf ^ 1][t] = cjn.x; cja[buf ^ 1][t] = cjn.y; cjb[buf ^ 1][t] = cjn.z;
        }

        __syncthreads();

        // ---- mma: ldmatrix fragments + 32 mma -----------------------------
#pragma unroll
        for (int ks = 0; ks < 2; ks++) {
            unsigned af0[4], af1[4];
            ldmatrix_x4(af0, aaddr[0][ks]);
            ldmatrix_x4(af1, aaddr[1][ks]);
            unsigned b0a[4], b0b[4], b1a[4], b1b[4];
            ldmatrix_x4(b0a, baddr[ks][0][0]);
            ldmatrix_x4(b0b, baddr[ks][0][1]);
            ldmatrix_x4(b1a, baddr[ks][1][0]);
            ldmatrix_x4(b1b, baddr[ks][1][1]);
#pragma unroll
            for (int nt = 0; nt < 8; nt++) {
                unsigned b0 = (nt < 4) ? b0a[nt] : b0b[nt - 4];
                unsigned b1 = (nt < 4) ? b1a[nt] : b1b[nt - 4];
                mma_bf16(acc[0][nt], af0, b0, b1);
                mma_bf16(acc[1][nt], af1, b0, b1);
            }
        }
        mcur = mnext;
    }

    sum_s[half][r] = rsum;
    __syncthreads();

    // ---- (1) out = att * inv (pure stores; mma fragment layout) -----------
#pragma unroll
    for (int mt = 0; mt < 2; mt++) {
        const int rl0 = warp_m + mt * 16 + g;
        const int rl1 = rl0 + 8;
        const float inv0 = 1.f / (sum_s[0][rl0] + sum_s[1][rl0]);
        const float inv1 = 1.f / (sum_s[0][rl1] + sum_s[1][rl1]);
#pragma unroll
        for (int nt = 0; nt < 8; nt++) {
            const int col = head * HEAD_F + warp_n + nt * 8 + 2 * tig;
            *(float2*)&out[(n0 + rl0) * OUT_F + col] =
                make_float2(acc[mt][nt][0] * inv0, acc[mt][nt][1] * inv0);
            *(float2*)&out[(n0 + rl1) * OUT_F + col] =
                make_float2(acc[mt][nt][2] * inv1, acc[mt][nt][3] * inv1);
        }
    }

    // ---- (2) fused residual: out += x @ W_r_head + bias (FFMA2) -----------
    {
        const int tx = t & 15, ty = t >> 4;
        float* As = (float*)P_s;           // [128][20]
        float* Bs = (float*)Ht;            // [16][128]
        unsigned long long racc[8][4];
#pragma unroll
        for (int i = 0; i < 8; i++)
#pragma unroll
            for (int j = 0; j < 4; j++) racc[i][j] = 0ull;

        for (int k0 = 0; k0 < IN_F; k0 += 16) {
            __syncthreads();
#pragma unroll
            for (int i = 0; i < 2; i++) {
                int idx = t + i * 256;
                int rr = idx >> 2, kq = (idx & 3) * 4;
                float4 v = *(const float4*)&x[(n0 + rr) * IN_F + k0 + kq];
                *(float4*)&As[rr * 20 + kq] = v;
            }
#pragma unroll
            for (int i = 0; i < 2; i++) {
                int idx = t + i * 256;
                int kk = idx >> 5, c4 = (idx & 31) * 4;
                float4 v = *(const float4*)&W_r[(k0 + kk) * OUT_F + head * HEAD_F + c4];
                *(float4*)&Bs[kk * 128 + c4] = v;
            }
            __syncthreads();
#pragma unroll
            for (int k = 0; k < 16; k++) {
                ulonglong2 b0 = *(const ulonglong2*)&Bs[k * 128 + tx * 8];
                ulonglong2 b1 = *(const ulonglong2*)&Bs[k * 128 + tx * 8 + 4];
#pragma unroll
                for (int i = 0; i < 8; i++) {
                    unsigned long long av = pack2(As[(ty * 8 + i) * 20 + k]);
                    ffma2(racc[i][0], av, b0.x);
                    ffma2(racc[i][1], av, b0.y);
                    ffma2(racc[i][2], av, b1.x);
                    ffma2(racc[i][3], av, b1.y);
                }
            }
        }

#pragma unroll
        for (int i = 0; i < 8; i++) {
            int rr = n0 + ty * 8 + i;
            int cc = head * HEAD_F + tx * 8;
            float2 a0 = unpack2(racc[i][0]), a1 = unpack2(racc[i][1]);
            float2 a2 = unpack2(racc[i][2]), a3 = unpack2(racc[i][3]);
            float4 bs0 = *(const float4*)&bias[cc];
            float4 bs1 = *(const float4*)&bias[cc + 4];
            float4 v0 = *(float4*)&out[rr * OUT_F + cc];
            float4 v1 = *(float4*)&out[rr * OUT_F + cc + 4];
            v0.x += a0.x + bs0.x; v0.y += a0.y + bs0.y;
            v0.z += a1.x + bs0.z; v0.w += a1.y + bs0.w;
            v1.x += a2.x + bs1.x; v1.y += a2.y + bs1.y;
            v1.z += a3.x + bs1.z; v1.w += a3.y + bs1.w;
            *(float4*)&out[rr * OUT_F + cc]     = v0;
            *(float4*)&out[rr * OUT_F + cc + 4] = v1;
        }
    }
}

// ---------------------------------------------------------------------------
extern "C" void kernel_launch(void* const* d_in, const int* in_sizes, int n_in,
                              void* d_out, int out_size)
{
    const float* x     = (const float*)d_in[0];
    const int*   graph = (const int*)  d_in[1];
    const float* W     = (const float*)d_in[2];
    const float* w_i   = (const float*)d_in[3];
    const float* w_j   = (const float*)d_in[4];
    const float* W_r   = (const float*)d_in[5];
    const float* bias  = (const float*)d_in[6];
    float* out = (float*)d_out;

    maskt_kernel<<<dim3(N_NODES / 32, N_NODES / 256), 256>>>(graph);
    gemm_kernel<<<dim3(N_NODES / 128, OUT_F / 128), 256>>>(x, W);
    hT_kernel<<<dim3(N_NODES / 32, OUT_F / 32), 256>>>();
    coe_kernel<<<dim3(N_NODES / 8, HEADS), 256>>>(w_i, w_j);
    attn_kernel<<<dim3(N_NODES / 128, HEADS), 256>>>(x, W_r, bias, out);
}

// round 9
// speedup vs baseline: 4.8350x; 1.3106x over previous
#include <cuda_runtime.h>
#include <cuda_bf16.h>

#define N_NODES 4096
#define IN_F    512
#define OUT_F   1024
#define HEADS   8
#define HEAD_F  128

// Scratch (device globals — no allocation allowed)
__device__ float          g_h    [N_NODES * OUT_F];            // h [n][head*128+f]
__device__ float4         g_ci4  [HEADS * N_NODES];            // (ci, e^ci, e^{0.2ci}, -)
__device__ float4         g_cj4  [HEADS * N_NODES];            // (cj, e^cj, e^{0.2cj}, -)
__device__ unsigned short g_hT16 [OUT_F * N_NODES];            // bf16 h^T [head*128+f][n]
__device__ unsigned short g_x16  [N_NODES * IN_F];             // bf16 x [n][k]
__device__ unsigned short g_WT16 [OUT_F * IN_F];               // bf16 W^T [head*128+f][k]
__device__ unsigned int   g_maskT[(N_NODES / 32) * N_NODES];   // word [mw][n], bit j = graph[mw*32+j][n]>0

// ---- helpers --------------------------------------------------------------
__device__ __forceinline__ unsigned smem_u32(const void* p) {
    unsigned a;
    asm("{ .reg .u64 t; cvta.to.shared.u64 t, %1; cvt.u32.u64 %0, t; }" : "=r"(a) : "l"(p));
    return a;
}
__device__ __forceinline__ void ffma2(unsigned long long& d, unsigned long long a,
                                      unsigned long long b) {
    asm("fma.rn.f32x2 %0, %1, %2, %0;" : "+l"(d) : "l"(a), "l"(b));
}
__device__ __forceinline__ unsigned long long pack2(float x) {
    unsigned long long r;
    asm("mov.b64 %0, {%1, %1};" : "=l"(r) : "f"(x));
    return r;
}
__device__ __forceinline__ float2 unpack2(unsigned long long u) {
    float2 f;
    asm("mov.b64 {%0, %1}, %2;" : "=f"(f.x), "=f"(f.y) : "l"(u));
    return f;
}
__device__ __forceinline__ void mma_bf16(float* d, const unsigned* a,
                                         unsigned b0, unsigned b1) {
    asm volatile(
        "mma.sync.aligned.m16n8k16.row.col.f32.bf16.bf16.f32 "
        "{%0,%1,%2,%3}, {%4,%5,%6,%7}, {%8,%9}, {%0,%1,%2,%3};"
        : "+f"(d[0]), "+f"(d[1]), "+f"(d[2]), "+f"(d[3])
        : "r"(a[0]), "r"(a[1]), "r"(a[2]), "r"(a[3]), "r"(b0), "r"(b1));
}
__device__ __forceinline__ void ldmatrix_x4(unsigned* d, unsigned addr) {
    asm volatile("ldmatrix.sync.aligned.m8n8.x4.shared.b16 {%0,%1,%2,%3}, [%4];"
        : "=r"(d[0]), "=r"(d[1]), "=r"(d[2]), "=r"(d[3]) : "r"(addr));
}
__device__ __forceinline__ unsigned pack_bf16x2(float lo, float hi) {
    unsigned u;
    asm("cvt.rn.bf16x2.f32 %0, %1, %2;" : "=r"(u) : "f"(hi), "f"(lo));
    return u;
}
__device__ __forceinline__ float2 unpack_bf16x2(unsigned u) {
    float2 r;
    r.x = __uint_as_float(u << 16);
    r.y = __uint_as_float(u & 0xffff0000u);
    return r;
}

// ---------------------------------------------------------------------------
// x -> bf16 (g_x16), k-contiguous
// ---------------------------------------------------------------------------
__global__ __launch_bounds__(256) void x16_kernel(const float* __restrict__ x)
{
    int i = blockIdx.x * 256 + threadIdx.x;          // word index
    float2 v = *(const float2*)&x[i * 2];
    ((unsigned*)g_x16)[i] = pack_bf16x2(v.x, v.y);
}

// ---------------------------------------------------------------------------
// W[h][k][f] -> g_WT16[(h*128+f)][k] bf16 (32x32 tile transpose)
// ---------------------------------------------------------------------------
__global__ __launch_bounds__(256) void wT_kernel(const float* __restrict__ W)
{
    __shared__ float s[32][33];
    const int h = blockIdx.z, k0 = blockIdx.x * 32, f0 = blockIdx.y * 32;
    const int t = threadIdx.x;
#pragma unroll
    for (int i = 0; i < 4; i++) {
        int idx = i * 256 + t, kk = idx >> 5, ff = idx & 31;
        s[kk][ff] = W[h * (IN_F * HEAD_F) + (k0 + kk) * HEAD_F + f0 + ff];
    }
    __syncthreads();
#pragma unroll
    for (int i = 0; i < 4; i++) {
        int idx = i * 256 + t, ff = idx >> 5, kk = idx & 31;
        *(__nv_bfloat16*)&g_WT16[(h * HEAD_F + f0 + ff) * IN_F + k0 + kk] =
            __float2bfloat16(s[kk][ff]);
    }
}

// ---------------------------------------------------------------------------
// bf16 GEMM: g_h[n][head*128+f] = x @ W  via mma.sync (tensor pipe).
// CTA = 128 rows x 1 head; same warp/fragment layout as attn.
// ---------------------------------------------------------------------------
__global__ __launch_bounds__(256, 2) void gemm_bf16_kernel()
{
    constexpr int PST = 20;
    __shared__ unsigned As_[128 * PST];
    __shared__ unsigned Bs_[128 * PST];

    const int t = threadIdx.x;
    const int w = t >> 5, lane = t & 31;
    const int g = lane >> 2, tig = lane & 3;
    const int warp_m = (w & 3) * 32;
    const int warp_f = (w >> 2) * 64;
    const int n0 = blockIdx.x * 128, head = blockIdx.y;

    const unsigned Ab = smem_u32(As_), Bb = smem_u32(Bs_);
    unsigned aaddr[2][2], baddr[2][2][2];
    {
        int arow = warp_m + (lane & 15);
        int ak   = (lane >> 4) << 2;
#pragma unroll
        for (int mt = 0; mt < 2; mt++)
#pragma unroll
            for (int ks = 0; ks < 2; ks++)
                aaddr[mt][ks] = Ab + 4u * ((arow + mt * 16) * PST + ks * 8 + ak);
        int brow = warp_f + (lane >> 3) * 8 + (lane & 7);
#pragma unroll
        for (int ks = 0; ks < 2; ks++)
#pragma unroll
            for (int hf = 0; hf < 2; hf++)
#pragma unroll
                for (int ng = 0; ng < 2; ng++)
                    baddr[ks][hf][ng] = Bb + 4u * ((brow + ng * 32) * PST + ks * 8 + hf * 4);
    }

    float acc[2][8][4];
#pragma unroll
    for (int mt = 0; mt < 2; mt++)
#pragma unroll
        for (int nt = 0; nt < 8; nt++)
#pragma unroll
            for (int q = 0; q < 4; q++) acc[mt][nt][q] = 0.f;

    const uint4* xg = (const uint4*)g_x16;
    const uint4* wg = (const uint4*)g_WT16;
    const int sr = t >> 2, sq = t & 3;     // staging row/quad

    for (int k0 = 0; k0 < IN_F; k0 += 32) {
        const int kq = k0 >> 3;            // uint4 offset within row (64/row)
        uint4 a0 = __ldg(&xg[(n0 + sr) * 64 + kq + sq]);
        uint4 a1 = __ldg(&xg[(n0 + sr + 64) * 64 + kq + sq]);
        uint4 b0 = __ldg(&wg[(head * 128 + sr) * 64 + kq + sq]);
        uint4 b1 = __ldg(&wg[(head * 128 + sr + 64) * 64 + kq + sq]);
        __syncthreads();   // prev mma done
        *(uint4*)&As_[sr * PST + sq * 4]        = a0;
        *(uint4*)&As_[(sr + 64) * PST + sq * 4] = a1;
        *(uint4*)&Bs_[sr * PST + sq * 4]        = b0;
        *(uint4*)&Bs_[(sr + 64) * PST + sq * 4] = b1;
        __syncthreads();

#pragma unroll
        for (int ks = 0; ks < 2; ks++) {
            unsigned af0[4], af1[4];
            ldmatrix_x4(af0, aaddr[0][ks]);
            ldmatrix_x4(af1, aaddr[1][ks]);
            unsigned b0a[4], b0b[4], b1a[4], b1b[4];
            ldmatrix_x4(b0a, baddr[ks][0][0]);
            ldmatrix_x4(b0b, baddr[ks][0][1]);
            ldmatrix_x4(b1a, baddr[ks][1][0]);
            ldmatrix_x4(b1b, baddr[ks][1][1]);
#pragma unroll
            for (int nt = 0; nt < 8; nt++) {
                unsigned bb0 = (nt < 4) ? b0a[nt] : b0b[nt - 4];
                unsigned bb1 = (nt < 4) ? b1a[nt] : b1b[nt - 4];
                mma_bf16(acc[0][nt], af0, bb0, bb1);
                mma_bf16(acc[1][nt], af1, bb0, bb1);
            }
        }
    }

#pragma unroll
    for (int mt = 0; mt < 2; mt++) {
        const int rl0 = warp_m + mt * 16 + g;
        const int rl1 = rl0 + 8;
#pragma unroll
        for (int nt = 0; nt < 8; nt++) {
            const int col = head * HEAD_F + warp_f + nt * 8 + 2 * tig;
            *(float2*)&g_h[(n0 + rl0) * OUT_F + col] =
                make_float2(acc[mt][nt][0], acc[mt][nt][1]);
            *(float2*)&g_h[(n0 + rl1) * OUT_F + col] =
                make_float2(acc[mt][nt][2], acc[mt][nt][3]);
        }
    }
}

// ---------------------------------------------------------------------------
// coe: per (head,n) dot products + precomputed exponentials
// ---------------------------------------------------------------------------
__global__ __launch_bounds__(256) void coe_kernel(
    const float* __restrict__ wi, const float* __restrict__ wj)
{
    int w = threadIdx.x >> 5, lane = threadIdx.x & 31;
    int n = blockIdx.x * 8 + w, h = blockIdx.y;
    float4 hv = *(const float4*)&g_h[n * OUT_F + h * HEAD_F + lane * 4];
    float4 a  = *(const float4*)&wi[h * HEAD_F + lane * 4];
    float4 b  = *(const float4*)&wj[h * HEAD_F + lane * 4];
    float si = hv.x * a.x + hv.y * a.y + hv.z * a.z + hv.w * a.w;
    float sj = hv.x * b.x + hv.y * b.y + hv.z * b.z + hv.w * b.w;
#pragma unroll
    for (int o = 16; o; o >>= 1) {
        si += __shfl_xor_sync(0xffffffffu, si, o);
        sj += __shfl_xor_sync(0xffffffffu, sj, o);
    }
    if (lane == 0) {
        g_ci4[h * N_NODES + n] = make_float4(si, __expf(si), __expf(0.2f * si), 0.f);
        g_cj4[h * N_NODES + n] = make_float4(sj, __expf(sj), __expf(0.2f * sj), 0.f);
    }
}

// ---------------------------------------------------------------------------
// Transposed bitmask: g_maskT[mw*N + n] bit j = graph[mw*32+j][n] > 0
// ---------------------------------------------------------------------------
__global__ __launch_bounds__(256) void maskt_kernel(const int* __restrict__ graph)
{
    int n  = blockIdx.y * 256 + threadIdx.x;
    int mw = blockIdx.x;
    const int* gp = &graph[(mw * 32) * N_NODES + n];
    unsigned w = 0;
#pragma unroll
    for (int j = 0; j < 32; j++)
        w |= (unsigned)(__ldg(&gp[j * N_NODES]) > 0) << j;
    g_maskT[mw * N_NODES + n] = w;
}

// ---------------------------------------------------------------------------
// h -> bf16 transpose: g_hT16[hf][n] = bf16(g_h[n][hf])
// ---------------------------------------------------------------------------
__global__ __launch_bounds__(256) void hT_kernel()
{
    __shared__ float s[32][33];
    const int n0 = blockIdx.x * 32, c0 = blockIdx.y * 32, t = threadIdx.x;
#pragma unroll
    for (int i = 0; i < 4; i++) {
        int idx = i * 256 + t, rr = idx >> 5, cc = idx & 31;
        s[rr][cc] = g_h[(n0 + rr) * OUT_F + c0 + cc];
    }
    __syncthreads();
#pragma unroll
    for (int i = 0; i < 4; i++) {
        int idx = i * 256 + t, cc = idx >> 5, nn = idx & 31;
        *(__nv_bfloat16*)&g_hT16[(c0 + cc) * N_NODES + n0 + nn] =
            __float2bfloat16(s[nn][cc]);
    }
}

// ---------------------------------------------------------------------------
// Attention (mma.sync bf16 + ldmatrix) with FUSED residual GEMM + bias.
// ---------------------------------------------------------------------------
__global__ __launch_bounds__(256, 2) void attn_kernel(
    const float* __restrict__ x, const float* __restrict__ W_r,
    const float* __restrict__ bias, float* __restrict__ out)
{
    constexpr int PST = 20;
    __shared__ unsigned P_s[128 * PST];    // also reused as As[128][20] (fp32)
    __shared__ unsigned Ht [128 * PST];    // also reused as Bs[16][128] (fp32)
    __shared__ float cjx[2][32], cja[2][32], cjb[2][32];
    __shared__ float sum_s[2][128];

    const int t    = threadIdx.x;
    const int w    = t >> 5;
    const int lane = t & 31;
    const int g    = lane >> 2;
    const int tig  = lane & 3;
    const int warp_m = (w & 3) * 32;
    const int warp_n = (w >> 2) * 64;
    const int n0   = blockIdx.x * 128;
    const int head = blockIdx.y;

    const unsigned Pb = smem_u32(P_s), Hb = smem_u32(Ht);
    unsigned aaddr[2][2], baddr[2][2][2];
    {
        int arow = warp_m + (lane & 15);
        int ak   = (lane >> 4) << 2;
#pragma unroll
        for (int mt = 0; mt < 2; mt++)
#pragma unroll
            for (int ks = 0; ks < 2; ks++)
                aaddr[mt][ks] = Pb + 4u * ((arow + mt * 16) * PST + ks * 8 + ak);
        int brow = warp_n + (lane >> 3) * 8 + (lane & 7);
#pragma unroll
        for (int ks = 0; ks < 2; ks++)
#pragma unroll
            for (int hf = 0; hf < 2; hf++)
#pragma unroll
                for (int ng = 0; ng < 2; ng++)
                    baddr[ks][hf][ng] = Hb + 4u * ((brow + ng * 32) * PST + ks * 8 + hf * 4);
    }

    const int r    = t & 127;
    const int half = t >> 7;
    const float4 ci = g_ci4[head * N_NODES + n0 + r];
    float rsum = 0.f;

    float acc[2][8][4];
#pragma unroll
    for (int mt = 0; mt < 2; mt++)
#pragma unroll
        for (int nt = 0; nt < 8; nt++)
#pragma unroll
            for (int q = 0; q < 4; q++) acc[mt][nt][q] = 0.f;

    if (t < 32) {
        float4 c4 = __ldg(&g_cj4[head * N_NODES + t]);
        cjx[0][t] = c4.x; cja[0][t] = c4.y; cjb[0][t] = c4.z;
    }
    unsigned mcur = __ldg(&g_maskT[n0 + r]);

    const int hTf = t >> 2, hTq = t & 3;

    for (int tile = 0; tile < N_NODES / 32; ++tile) {
        const int m0  = tile * 32;
        const int buf = tile & 1;

        uint4 hv0 = __ldg(&((const uint4*)g_hT16)[(head * 128 + hTf) * (N_NODES / 8) + (m0 >> 3) + hTq]);
        uint4 hv1 = __ldg(&((const uint4*)g_hT16)[(head * 128 + hTf + 64) * (N_NODES / 8) + (m0 >> 3) + hTq]);
        float4 cjn = make_float4(0.f, 0.f, 0.f, 0.f);
        if (t < 32 && tile + 1 < N_NODES / 32)
            cjn = __ldg(&g_cj4[head * N_NODES + (tile + 1) * 32 + t]);
        unsigned mnext = (tile + 1 < N_NODES / 32)
                         ? __ldg(&g_maskT[(tile + 1) * N_NODES + n0 + r]) : 0u;

        __syncthreads();

        unsigned pw[8];
#pragma unroll
        for (int j2 = 0; j2 < 8; j2++) {
            const int k = half * 16 + j2 * 2;
            float s0 = ci.x + cjx[buf][k];
            float pa0 = s0 > 0.f ? ci.y : ci.z;
            float pb0 = s0 > 0.f ? cja[buf][k] : cjb[buf][k];
            float p0 = ((mcur >> k) & 1u) ? pa0 * pb0 : 0.f;
            float s1 = ci.x + cjx[buf][k + 1];
            float pa1 = s1 > 0.f ? ci.y : ci.z;
            float pb1 = s1 > 0.f ? cja[buf][k + 1] : cjb[buf][k + 1];
            float p1 = ((mcur >> (k + 1)) & 1u) ? pa1 * pb1 : 0.f;
            pw[j2] = pack_bf16x2(p0, p1);
            float2 pr = unpack_bf16x2(pw[j2]);
            rsum += pr.x + pr.y;
        }
        *(uint4*)&P_s[r * PST + half * 8]     = make_uint4(pw[0], pw[1], pw[2], pw[3]);
        *(uint4*)&P_s[r * PST + half * 8 + 4] = make_uint4(pw[4], pw[5], pw[6], pw[7]);

        *(uint4*)&Ht[hTf * PST + hTq * 4]        = hv0;
        *(uint4*)&Ht[(hTf + 64) * PST + hTq * 4] = hv1;
        if (t < 32 && tile + 1 < N_NODES / 32) {
            cjx[buf ^ 1][t] = cjn.x; cja[buf ^ 1][t] = cjn.y; cjb[buf ^ 1][t] = cjn.z;
        }

        __syncthreads();

#pragma unroll
        for (int ks = 0; ks < 2; ks++) {
            unsigned af0[4], af1[4];
            ldmatrix_x4(af0, aaddr[0][ks]);
            ldmatrix_x4(af1, aaddr[1][ks]);
            unsigned b0a[4], b0b[4], b1a[4], b1b[4];
            ldmatrix_x4(b0a, baddr[ks][0][0]);
            ldmatrix_x4(b0b, baddr[ks][0][1]);
            ldmatrix_x4(b1a, baddr[ks][1][0]);
            ldmatrix_x4(b1b, baddr[ks][1][1]);
#pragma unroll
            for (int nt = 0; nt < 8; nt++) {
                unsigned b0 = (nt < 4) ? b0a[nt] : b0b[nt - 4];
                unsigned b1 = (nt < 4) ? b1a[nt] : b1b[nt - 4];
                mma_bf16(acc[0][nt], af0, b0, b1);
                mma_bf16(acc[1][nt], af1, b0, b1);
            }
        }
        mcur = mnext;
    }

    sum_s[half][r] = rsum;
    __syncthreads();

    // (1) out = att * inv
#pragma unroll
    for (int mt = 0; mt < 2; mt++) {
        const int rl0 = warp_m + mt * 16 + g;
        const int rl1 = rl0 + 8;
        const float inv0 = 1.f / (sum_s[0][rl0] + sum_s[1][rl0]);
        const float inv1 = 1.f / (sum_s[0][rl1] + sum_s[1][rl1]);
#pragma unroll
        for (int nt = 0; nt < 8; nt++) {
            const int col = head * HEAD_F + warp_n + nt * 8 + 2 * tig;
            *(float2*)&out[(n0 + rl0) * OUT_F + col] =
                make_float2(acc[mt][nt][0] * inv0, acc[mt][nt][1] * inv0);
            *(float2*)&out[(n0 + rl1) * OUT_F + col] =
                make_float2(acc[mt][nt][2] * inv1, acc[mt][nt][3] * inv1);
        }
    }

    // (2) fused residual: out += x @ W_r_head + bias (FFMA2, fp32)
    {
        const int tx = t & 15, ty = t >> 4;
        float* As = (float*)P_s;
        float* Bs = (float*)Ht;
        unsigned long long racc[8][4];
#pragma unroll
        for (int i = 0; i < 8; i++)
#pragma unroll
            for (int j = 0; j < 4; j++) racc[i][j] = 0ull;

        for (int k0 = 0; k0 < IN_F; k0 += 16) {
            __syncthreads();
#pragma unroll
            for (int i = 0; i < 2; i++) {
                int idx = t + i * 256;
                int rr = idx >> 2, kq = (idx & 3) * 4;
                float4 v = *(const float4*)&x[(n0 + rr) * IN_F + k0 + kq];
                *(float4*)&As[rr * 20 + kq] = v;
            }
#pragma unroll
            for (int i = 0; i < 2; i++) {
                int idx = t + i * 256;
                int kk = idx >> 5, c4 = (idx & 31) * 4;
                float4 v = *(const float4*)&W_r[(k0 + kk) * OUT_F + head * HEAD_F + c4];
                *(float4*)&Bs[kk * 128 + c4] = v;
            }
            __syncthreads();
#pragma unroll
            for (int k = 0; k < 16; k++) {
                ulonglong2 b0 = *(const ulonglong2*)&Bs[k * 128 + tx * 8];
                ulonglong2 b1 = *(const ulonglong2*)&Bs[k * 128 + tx * 8 + 4];
#pragma unroll
                for (int i = 0; i < 8; i++) {
                    unsigned long long av = pack2(As[(ty * 8 + i) * 20 + k]);
                    ffma2(racc[i][0], av, b0.x);
                    ffma2(racc[i][1], av, b0.y);
                    ffma2(racc[i][2], av, b1.x);
                    ffma2(racc[i][3], av, b1.y);
                }
            }
        }

#pragma unroll
        for (int i = 0; i < 8; i++) {
            int rr = n0 + ty * 8 + i;
            int cc = head * HEAD_F + tx * 8;
            float2 a0 = unpack2(racc[i][0]), a1 = unpack2(racc[i][1]);
            float2 a2 = unpack2(racc[i][2]), a3 = unpack2(racc[i][3]);
            float4 bs0 = *(const float4*)&bias[cc];
            float4 bs1 = *(const float4*)&bias[cc + 4];
            float4 v0 = *(float4*)&out[rr * OUT_F + cc];
            float4 v1 = *(float4*)&out[rr * OUT_F + cc + 4];
            v0.x += a0.x + bs0.x; v0.y += a0.y + bs0.y;
            v0.z += a1.x + bs0.z; v0.w += a1.y + bs0.w;
            v1.x += a2.x + bs1.x; v1.y += a2.y + bs1.y;
            v1.z += a3.x + bs1.z; v1.w += a3.y + bs1.w;
            *(float4*)&out[rr * OUT_F + cc]     = v0;
            *(float4*)&out[rr * OUT_F + cc + 4] = v1;
        }
    }
}

// ---------------------------------------------------------------------------
extern "C" void kernel_launch(void* const* d_in, const int* in_sizes, int n_in,
                              void* d_out, int out_size)
{
    const float* x     = (const float*)d_in[0];
    const int*   graph = (const int*)  d_in[1];
    const float* W     = (const float*)d_in[2];
    const float* w_i   = (const float*)d_in[3];
    const float* w_j   = (const float*)d_in[4];
    const float* W_r   = (const float*)d_in[5];
    const float* bias  = (const float*)d_in[6];
    float* out = (float*)d_out;

    x16_kernel<<<(N_NODES * IN_F / 2) / 256, 256>>>(x);
    wT_kernel<<<dim3(IN_F / 32, HEAD_F / 32, HEADS), 256>>>(W);
    maskt_kernel<<<dim3(N_NODES / 32, N_NODES / 256), 256>>>(graph);
    gemm_bf16_kernel<<<dim3(N_NODES / 128, HEADS), 256>>>();
    hT_kernel<<<dim3(N_NODES / 32, OUT_F / 32), 256>>>();
    coe_kernel<<<dim3(N_NODES / 8, HEADS), 256>>>(w_i, w_j);
    attn_kernel<<<dim3(N_NODES / 128, HEADS), 256>>>(x, W_r, bias, out);
}

// round 10
// speedup vs baseline: 6.2349x; 1.2895x over previous
#include <cuda_runtime.h>
#include <cuda_bf16.h>

#define N_NODES 4096
#define IN_F    512
#define OUT_F   1024
#define HEADS   8
#define HEAD_F  128

// Scratch (device globals — no allocation allowed)
__device__ float          g_h    [N_NODES * OUT_F];            // h [n][head*128+f]
__device__ float4         g_ci4  [HEADS * N_NODES];            // (ci, e^ci, e^{0.2ci}, -)
__device__ float4         g_cj4  [HEADS * N_NODES];            // (cj, e^cj, e^{0.2cj}, -)
__device__ unsigned short g_hT16 [OUT_F * N_NODES];            // bf16 h^T [head*128+f][n]
__device__ unsigned short g_xs16 [N_NODES * 1024];             // bf16 [x_hi(512) | x_lo(512)] per row
__device__ unsigned short g_WT16 [OUT_F * IN_F];               // bf16 W^T [head*128+f][k]
__device__ unsigned short g_WrT16[OUT_F * 1536];               // bf16 [Wr_hi | Wr_hi | Wr_lo] ^T rows
__device__ unsigned int   g_maskT[(N_NODES / 32) * N_NODES];   // word [mw][n], bit j = graph[mw*32+j][n]>0

// ---- helpers --------------------------------------------------------------
__device__ __forceinline__ unsigned smem_u32(const void* p) {
    unsigned a;
    asm("{ .reg .u64 t; cvta.to.shared.u64 t, %1; cvt.u32.u64 %0, t; }" : "=r"(a) : "l"(p));
    return a;
}
__device__ __forceinline__ void mma_bf16(float* d, const unsigned* a,
                                         unsigned b0, unsigned b1) {
    asm volatile(
        "mma.sync.aligned.m16n8k16.row.col.f32.bf16.bf16.f32 "
        "{%0,%1,%2,%3}, {%4,%5,%6,%7}, {%8,%9}, {%0,%1,%2,%3};"
        : "+f"(d[0]), "+f"(d[1]), "+f"(d[2]), "+f"(d[3])
        : "r"(a[0]), "r"(a[1]), "r"(a[2]), "r"(a[3]), "r"(b0), "r"(b1));
}
__device__ __forceinline__ void ldmatrix_x4(unsigned* d, unsigned addr) {
    asm volatile("ldmatrix.sync.aligned.m8n8.x4.shared.b16 {%0,%1,%2,%3}, [%4];"
        : "=r"(d[0]), "=r"(d[1]), "=r"(d[2]), "=r"(d[3]) : "r"(addr));
}
__device__ __forceinline__ unsigned pack_bf16x2(float lo, float hi) {
    unsigned u;
    asm("cvt.rn.bf16x2.f32 %0, %1, %2;" : "=r"(u) : "f"(hi), "f"(lo));
    return u;
}
__device__ __forceinline__ float2 unpack_bf16x2(unsigned u) {
    float2 r;
    r.x = __uint_as_float(u << 16);
    r.y = __uint_as_float(u & 0xffff0000u);
    return r;
}

// ---------------------------------------------------------------------------
// x -> split bf16: g_xs16[n] = [hi(512) | lo(512)]
// ---------------------------------------------------------------------------
__global__ __launch_bounds__(256) void xsplit_kernel(const float* __restrict__ x)
{
    int i = blockIdx.x * 256 + threadIdx.x;       // word index (2 floats)
    int n = i >> 8, kw = i & 255;
    float2 v = *(const float2*)&x[n * IN_F + kw * 2];
    unsigned hi = pack_bf16x2(v.x, v.y);
    float2 hf = unpack_bf16x2(hi);
    unsigned lo = pack_bf16x2(v.x - hf.x, v.y - hf.y);
    ((unsigned*)g_xs16)[n * 512 + kw]       = hi;
    ((unsigned*)g_xs16)[n * 512 + 256 + kw] = lo;
}

// ---------------------------------------------------------------------------
// W[h][k][f] -> g_WT16[(h*128+f)][k] bf16 (32x32 tile transpose)
// ---------------------------------------------------------------------------
__global__ __launch_bounds__(256) void wT_kernel(const float* __restrict__ W)
{
    __shared__ float s[32][33];
    const int h = blockIdx.z, k0 = blockIdx.x * 32, f0 = blockIdx.y * 32;
    const int t = threadIdx.x;
#pragma unroll
    for (int i = 0; i < 4; i++) {
        int idx = i * 256 + t, kk = idx >> 5, ff = idx & 31;
        s[kk][ff] = W[h * (IN_F * HEAD_F) + (k0 + kk) * HEAD_F + f0 + ff];
    }
    __syncthreads();
#pragma unroll
    for (int i = 0; i < 4; i++) {
        int idx = i * 256 + t, ff = idx >> 5, kk = idx & 31;
        *(__nv_bfloat16*)&g_WT16[(h * HEAD_F + f0 + ff) * IN_F + k0 + kk] =
            __float2bfloat16(s[kk][ff]);
    }
}

// ---------------------------------------------------------------------------
// W_r[k][c] -> g_WrT16[c][ [hi(512) | hi(512) | lo(512)] ]  (split transpose)
// ---------------------------------------------------------------------------
__global__ __launch_bounds__(256) void wrT_kernel(const float* __restrict__ W_r)
{
    __shared__ float s[32][33];
    const int k0 = blockIdx.x * 32, c0 = blockIdx.y * 32;
    const int t = threadIdx.x;
#pragma unroll
    for (int i = 0; i < 4; i++) {
        int idx = i * 256 + t, kk = idx >> 5, ff = idx & 31;
        s[kk][ff] = W_r[(k0 + kk) * OUT_F + c0 + ff];
    }
    __syncthreads();
#pragma unroll
    for (int i = 0; i < 4; i++) {
        int idx = i * 256 + t, ff = idx >> 5, kk = idx & 31;
        float v = s[kk][ff];
        __nv_bfloat16 hi = __float2bfloat16(v);
        __nv_bfloat16 lo = __float2bfloat16(v - __bfloat162float(hi));
        unsigned short hb = *(unsigned short*)&hi;
        unsigned short lb = *(unsigned short*)&lo;
        int row = (c0 + ff) * 1536;
        g_WrT16[row + (k0 + kk)]        = hb;
        g_WrT16[row + 512 + (k0 + kk)]  = hb;
        g_WrT16[row + 1024 + (k0 + kk)] = lb;
    }
}

// ---------------------------------------------------------------------------
// Transposed bitmask (int4 loads): g_maskT[mw*N+n] bit j = graph[mw*32+j][n]>0
// ---------------------------------------------------------------------------
__global__ __launch_bounds__(256) void maskt_kernel(const int* __restrict__ graph)
{
    const int mw = blockIdx.x;
    const int n4 = (blockIdx.y * 256 + threadIdx.x) * 4;
    const int4* gp = (const int4*)&graph[(mw * 32) * N_NODES + n4];
    unsigned w0 = 0, w1 = 0, w2 = 0, w3 = 0;
#pragma unroll
    for (int j = 0; j < 32; j++) {
        int4 gg = __ldg(&gp[j * (N_NODES / 4)]);
        w0 |= (unsigned)(gg.x > 0) << j;
        w1 |= (unsigned)(gg.y > 0) << j;
        w2 |= (unsigned)(gg.z > 0) << j;
        w3 |= (unsigned)(gg.w > 0) << j;
    }
    *(uint4*)&g_maskT[mw * N_NODES + n4] = make_uint4(w0, w1, w2, w3);
}

// ---------------------------------------------------------------------------
// bf16 GEMM: g_h = x_hi @ W (tensor pipe, double-buffered single-sync).
// ---------------------------------------------------------------------------
__global__ __launch_bounds__(256, 2) void gemm_bf16_kernel()
{
    constexpr int PST = 20;
    constexpr unsigned BUFB = 128 * PST * 4u;
    __shared__ unsigned A2[2][128 * PST];
    __shared__ unsigned B2[2][128 * PST];

    const int t = threadIdx.x;
    const int w = t >> 5, lane = t & 31;
    const int g = lane >> 2, tig = lane & 3;
    const int warp_m = (w & 3) * 32;
    const int warp_f = (w >> 2) * 64;
    const int n0 = blockIdx.x * 128, head = blockIdx.y;

    const unsigned Ab = smem_u32(A2[0]), Bb = smem_u32(B2[0]);
    unsigned aaddr[2][2], baddr[2][2][2];
    {
        int arow = warp_m + (lane & 15);
        int ak   = (lane >> 4) << 2;
#pragma unroll
        for (int mt = 0; mt < 2; mt++)
#pragma unroll
            for (int ks = 0; ks < 2; ks++)
                aaddr[mt][ks] = Ab + 4u * ((arow + mt * 16) * PST + ks * 8 + ak);
        int brow = warp_f + (lane >> 3) * 8 + (lane & 7);
#pragma unroll
        for (int ks = 0; ks < 2; ks++)
#pragma unroll
            for (int hf = 0; hf < 2; hf++)
#pragma unroll
                for (int ng = 0; ng < 2; ng++)
                    baddr[ks][hf][ng] = Bb + 4u * ((brow + ng * 32) * PST + ks * 8 + hf * 4);
    }

    float acc[2][8][4];
#pragma unroll
    for (int mt = 0; mt < 2; mt++)
#pragma unroll
        for (int nt = 0; nt < 8; nt++)
#pragma unroll
            for (int q = 0; q < 4; q++) acc[mt][nt][q] = 0.f;

    const uint4* xg = (const uint4*)g_xs16;     // row stride 128 u4; hi at [0,64)
    const uint4* wg = (const uint4*)g_WT16;     // row stride 64 u4
    const int sr = t >> 2, sq = t & 3;
    constexpr int S = 16;

    uint4 a0, a1, b0, b1;
    auto ldgS = [&](int s) {
        int kq = s * 4;
        a0 = __ldg(&xg[(n0 + sr) * 128 + kq + sq]);
        a1 = __ldg(&xg[(n0 + sr + 64) * 128 + kq + sq]);
        b0 = __ldg(&wg[(head * 128 + sr) * 64 + kq + sq]);
        b1 = __ldg(&wg[(head * 128 + sr + 64) * 64 + kq + sq]);
    };
    auto stsS = [&](int buf) {
        *(uint4*)&A2[buf][sr * PST + sq * 4]        = a0;
        *(uint4*)&A2[buf][(sr + 64) * PST + sq * 4] = a1;
        *(uint4*)&B2[buf][sr * PST + sq * 4]        = b0;
        *(uint4*)&B2[buf][(sr + 64) * PST + sq * 4] = b1;
    };

    ldgS(0); stsS(0);
    ldgS(1);
    __syncthreads();

    for (int s = 0; s < S; s++) {
        const unsigned mo = (s & 1) ? BUFB : 0u;
#pragma unroll
        for (int ks = 0; ks < 2; ks++) {
            unsigned af0[4], af1[4];
            ldmatrix_x4(af0, aaddr[0][ks] + mo);
            ldmatrix_x4(af1, aaddr[1][ks] + mo);
            unsigned b0a[4], b0b[4], b1a[4], b1b[4];
            ldmatrix_x4(b0a, baddr[ks][0][0] + mo);
            ldmatrix_x4(b0b, baddr[ks][0][1] + mo);
            ldmatrix_x4(b1a, baddr[ks][1][0] + mo);
            ldmatrix_x4(b1b, baddr[ks][1][1] + mo);
#pragma unroll
            for (int nt = 0; nt < 8; nt++) {
                unsigned bb0 = (nt < 4) ? b0a[nt] : b0b[nt - 4];
                unsigned bb1 = (nt < 4) ? b1a[nt] : b1b[nt - 4];
                mma_bf16(acc[0][nt], af0, bb0, bb1);
                mma_bf16(acc[1][nt], af1, bb0, bb1);
            }
        }
        if (s + 1 < S) {
            stsS((s + 1) & 1);
            if (s + 2 < S) ldgS(s + 2);
        }
        __syncthreads();
    }

#pragma unroll
    for (int mt = 0; mt < 2; mt++) {
        const int rl0 = warp_m + mt * 16 + g;
        const int rl1 = rl0 + 8;
#pragma unroll
        for (int nt = 0; nt < 8; nt++) {
            const int col = head * HEAD_F + warp_f + nt * 8 + 2 * tig;
            *(float2*)&g_h[(n0 + rl0) * OUT_F + col] =
                make_float2(acc[0 * 2 + 0][nt][0], acc[0][nt][1]);
            *(float2*)&g_h[(n0 + rl1) * OUT_F + col] =
                make_float2(acc[0][nt][2], acc[0][nt][3]);
            // mt handled via loop: fix indices below
        }
    }
    // NOTE: rewritten without the buggy shortcut above:
#pragma unroll
    for (int mt = 0; mt < 2; mt++) {
        const int rl0 = warp_m + mt * 16 + g;
        const int rl1 = rl0 + 8;
#pragma unroll
        for (int nt = 0; nt < 8; nt++) {
            const int col = head * HEAD_F + warp_f + nt * 8 + 2 * tig;
            *(float2*)&g_h[(n0 + rl0) * OUT_F + col] =
                make_float2(acc[mt][nt][0], acc[mt][nt][1]);
            *(float2*)&g_h[(n0 + rl1) * OUT_F + col] =
                make_float2(acc[mt][nt][2], acc[mt][nt][3]);
        }
    }
}

// ---------------------------------------------------------------------------
// Residual GEMM (tensor pipe, 3-term bf16 split, K=1536):
//   out += [x_hi|x_lo|x_hi] @ [Wr_hi|Wr_hi|Wr_lo]^T + bias
// ---------------------------------------------------------------------------
__global__ __launch_bounds__(256, 2) void res_kernel(
    const float* __restrict__ bias, float* __restrict__ out)
{
    constexpr int PST = 20;
    constexpr unsigned BUFB = 128 * PST * 4u;
    __shared__ unsigned A2[2][128 * PST];
    __shared__ unsigned B2[2][128 * PST];

    const int t = threadIdx.x;
    const int w = t >> 5, lane = t & 31;
    const int g = lane >> 2, tig = lane & 3;
    const int warp_m = (w & 3) * 32;
    const int warp_f = (w >> 2) * 64;
    const int n0 = blockIdx.x * 128, head = blockIdx.y;

    const unsigned Ab = smem_u32(A2[0]), Bb = smem_u32(B2[0]);
    unsigned aaddr[2][2], baddr[2][2][2];
    {
        int arow = warp_m + (lane & 15);
        int ak   = (lane >> 4) << 2;
#pragma unroll
        for (int mt = 0; mt < 2; mt++)
#pragma unroll
            for (int ks = 0; ks < 2; ks++)
                aaddr[mt][ks] = Ab + 4u * ((arow + mt * 16) * PST + ks * 8 + ak);
        int brow = warp_f + (lane >> 3) * 8 + (lane & 7);
#pragma unroll
        for (int ks = 0; ks < 2; ks++)
#pragma unroll
            for (int hf = 0; hf < 2; hf++)
#pragma unroll
                for (int ng = 0; ng < 2; ng++)
                    baddr[ks][hf][ng] = Bb + 4u * ((brow + ng * 32) * PST + ks * 8 + hf * 4);
    }

    float acc[2][8][4];
#pragma unroll
    for (int mt = 0; mt < 2; mt++)
#pragma unroll
        for (int nt = 0; nt < 8; nt++)
#pragma unroll
            for (int q = 0; q < 4; q++) acc[mt][nt][q] = 0.f;

    const uint4* xg = (const uint4*)g_xs16;     // row 128 u4: [hi|lo]
    const uint4* wg = (const uint4*)g_WrT16;    // row 192 u4
    const int sr = t >> 2, sq = t & 3;
    constexpr int S = 48;

    uint4 a0, a1, b0, b1;
    auto ldgS = [&](int s) {
        int k3 = s * 32;
        int ak = ((k3 < 1024) ? k3 : (k3 - 1024)) >> 3;
        int bk = k3 >> 3;
        a0 = __ldg(&xg[(n0 + sr) * 128 + ak + sq]);
        a1 = __ldg(&xg[(n0 + sr + 64) * 128 + ak + sq]);
        b0 = __ldg(&wg[(head * 128 + sr) * 192 + bk + sq]);
        b1 = __ldg(&wg[(head * 128 + sr + 64) * 192 + bk + sq]);
    };
    auto stsS = [&](int buf) {
        *(uint4*)&A2[buf][sr * PST + sq * 4]        = a0;
        *(uint4*)&A2[buf][(sr + 64) * PST + sq * 4] = a1;
        *(uint4*)&B2[buf][sr * PST + sq * 4]        = b0;
        *(uint4*)&B2[buf][(sr + 64) * PST + sq * 4] = b1;
    };

    ldgS(0); stsS(0);
    ldgS(1);
    __syncthreads();

    for (int s = 0; s < S; s++) {
        const unsigned mo = (s & 1) ? BUFB : 0u;
#pragma unroll
        for (int ks = 0; ks < 2; ks++) {
            unsigned af0[4], af1[4];
            ldmatrix_x4(af0, aaddr[0][ks] + mo);
            ldmatrix_x4(af1, aaddr[1][ks] + mo);
            unsigned b0a[4], b0b[4], b1a[4], b1b[4];
            ldmatrix_x4(b0a, baddr[ks][0][0] + mo);
            ldmatrix_x4(b0b, baddr[ks][0][1] + mo);
            ldmatrix_x4(b1a, baddr[ks][1][0] + mo);
            ldmatrix_x4(b1b, baddr[ks][1][1] + mo);
#pragma unroll
            for (int nt = 0; nt < 8; nt++) {
                unsigned bb0 = (nt < 4) ? b0a[nt] : b0b[nt - 4];
                unsigned bb1 = (nt < 4) ? b1a[nt] : b1b[nt - 4];
                mma_bf16(acc[0][nt], af0, bb0, bb1);
                mma_bf16(acc[1][nt], af1, bb0, bb1);
            }
        }
        if (s + 1 < S) {
            stsS((s + 1) & 1);
            if (s + 2 < S) ldgS(s + 2);
        }
        __syncthreads();
    }

#pragma unroll
    for (int mt = 0; mt < 2; mt++) {
        const int rl0 = warp_m + mt * 16 + g;
        const int rl1 = rl0 + 8;
#pragma unroll
        for (int nt = 0; nt < 8; nt++) {
            const int col = head * HEAD_F + warp_f + nt * 8 + 2 * tig;
            float2 bb = *(const float2*)&bias[col];
            float2 v0 = *(float2*)&out[(n0 + rl0) * OUT_F + col];
            v0.x += acc[mt][nt][0] + bb.x;
            v0.y += acc[mt][nt][1] + bb.y;
            *(float2*)&out[(n0 + rl0) * OUT_F + col] = v0;
            float2 v1 = *(float2*)&out[(n0 + rl1) * OUT_F + col];
            v1.x += acc[mt][nt][2] + bb.x;
            v1.y += acc[mt][nt][3] + bb.y;
            *(float2*)&out[(n0 + rl1) * OUT_F + col] = v1;
        }
    }
}

// ---------------------------------------------------------------------------
// coe: per (head,n) dot products + precomputed exponentials
// ---------------------------------------------------------------------------
__global__ __launch_bounds__(256) void coe_kernel(
    const float* __restrict__ wi, const float* __restrict__ wj)
{
    int w = threadIdx.x >> 5, lane = threadIdx.x & 31;
    int n = blockIdx.x * 8 + w, h = blockIdx.y;
    float4 hv = *(const float4*)&g_h[n * OUT_F + h * HEAD_F + lane * 4];
    float4 a  = *(const float4*)&wi[h * HEAD_F + lane * 4];
    float4 b  = *(const float4*)&wj[h * HEAD_F + lane * 4];
    float si = hv.x * a.x + hv.y * a.y + hv.z * a.z + hv.w * a.w;
    float sj = hv.x * b.x + hv.y * b.y + hv.z * b.z + hv.w * b.w;
#pragma unroll
    for (int o = 16; o; o >>= 1) {
        si += __shfl_xor_sync(0xffffffffu, si, o);
        sj += __shfl_xor_sync(0xffffffffu, sj, o);
    }
    if (lane == 0) {
        g_ci4[h * N_NODES + n] = make_float4(si, __expf(si), __expf(0.2f * si), 0.f);
        g_cj4[h * N_NODES + n] = make_float4(sj, __expf(sj), __expf(0.2f * sj), 0.f);
    }
}

// ---------------------------------------------------------------------------
// h -> bf16 transpose: g_hT16[hf][n] = bf16(g_h[n][hf])
// ---------------------------------------------------------------------------
__global__ __launch_bounds__(256) void hT_kernel()
{
    __shared__ float s[32][33];
    const int n0 = blockIdx.x * 32, c0 = blockIdx.y * 32, t = threadIdx.x;
#pragma unroll
    for (int i = 0; i < 4; i++) {
        int idx = i * 256 + t, rr = idx >> 5, cc = idx & 31;
        s[rr][cc] = g_h[(n0 + rr) * OUT_F + c0 + cc];
    }
    __syncthreads();
#pragma unroll
    for (int i = 0; i < 4; i++) {
        int idx = i * 256 + t, cc = idx >> 5, nn = idx & 31;
        *(__nv_bfloat16*)&g_hT16[(c0 + cc) * N_NODES + n0 + nn] =
            __float2bfloat16(s[nn][cc]);
    }
}

// ---------------------------------------------------------------------------
// Attention (mma.sync bf16 + ldmatrix), double-buffered, 1 sync/tile.
// CTA = 128 rows x 1 head. Iter t: build P/Ht(t+1) into buf^1, mma(t), sync.
// ---------------------------------------------------------------------------
__global__ __launch_bounds__(256, 2) void attn_kernel(float* __restrict__ out)
{
    constexpr int PST = 20;
    constexpr unsigned BUFB = 128 * PST * 4u;
    constexpr int T = N_NODES / 32;
    __shared__ unsigned P2[2][128 * PST];
    __shared__ unsigned H2[2][128 * PST];
    __shared__ float cjx[2][32], cja[2][32], cjb[2][32];
    __shared__ float sum_s[2][128];

    const int t = threadIdx.x;
    const int w = t >> 5, lane = t & 31;
    const int g = lane >> 2, tig = lane & 3;
    const int warp_m = (w & 3) * 32;
    const int warp_n = (w >> 2) * 64;
    const int n0 = blockIdx.x * 128, head = blockIdx.y;

    const unsigned Pb = smem_u32(P2[0]), Hb = smem_u32(H2[0]);
    unsigned aaddr[2][2], baddr[2][2][2];
    {
        int arow = warp_m + (lane & 15);
        int ak   = (lane >> 4) << 2;
#pragma unroll
        for (int mt = 0; mt < 2; mt++)
#pragma unroll
            for (int ks = 0; ks < 2; ks++)
                aaddr[mt][ks] = Pb + 4u * ((arow + mt * 16) * PST + ks * 8 + ak);
        int brow = warp_n + (lane >> 3) * 8 + (lane & 7);
#pragma unroll
        for (int ks = 0; ks < 2; ks++)
#pragma unroll
            for (int hf = 0; hf < 2; hf++)
#pragma unroll
                for (int ng = 0; ng < 2; ng++)
                    baddr[ks][hf][ng] = Hb + 4u * ((brow + ng * 32) * PST + ks * 8 + hf * 4);
    }

    const int r = t & 127, half = t >> 7;
    const float4 ci = g_ci4[head * N_NODES + n0 + r];
    float rsum = 0.f;

    float acc[2][8][4];
#pragma unroll
    for (int mt = 0; mt < 2; mt++)
#pragma unroll
        for (int nt = 0; nt < 8; nt++)
#pragma unroll
            for (int q = 0; q < 4; q++) acc[mt][nt][q] = 0.f;

    const int hTf = t >> 2, hTq = t & 3;
    const uint4* hTg = (const uint4*)g_hT16;

    // ---- P build into buffer `buf` for key tile `tile`, mask word m -------
    auto buildP = [&](int tile, int buf, unsigned m) {
        unsigned pw[8];
#pragma unroll
        for (int j2 = 0; j2 < 8; j2++) {
            const int k = half * 16 + j2 * 2;
            float s0 = ci.x + cjx[buf][k];
            float pa0 = s0 > 0.f ? ci.y : ci.z;
            float pb0 = s0 > 0.f ? cja[buf][k] : cjb[buf][k];
            float p0 = ((m >> k) & 1u) ? pa0 * pb0 : 0.f;
            float s1 = ci.x + cjx[buf][k + 1];
            float pa1 = s1 > 0.f ? ci.y : ci.z;
            float pb1 = s1 > 0.f ? cja[buf][k + 1] : cjb[buf][k + 1];
            float p1 = ((m >> (k + 1)) & 1u) ? pa1 * pb1 : 0.f;
            pw[j2] = pack_bf16x2(p0, p1);
            float2 pr = unpack_bf16x2(pw[j2]);
            rsum += pr.x + pr.y;
        }
        *(uint4*)&P2[buf][r * PST + half * 8]     = make_uint4(pw[0], pw[1], pw[2], pw[3]);
        *(uint4*)&P2[buf][r * PST + half * 8 + 4] = make_uint4(pw[4], pw[5], pw[6], pw[7]);
    };

    // ---- prologue: tiles 0 (built) and cj(1)/mask(1) staged ----------------
    if (t < 32) {
        float4 c4 = __ldg(&g_cj4[head * N_NODES + t]);
        cjx[0][t] = c4.x; cja[0][t] = c4.y; cjb[0][t] = c4.z;
    }
    unsigned mreg = __ldg(&g_maskT[n0 + r]);                       // mask(0)
    uint4 hv0 = __ldg(&hTg[(head * 128 + hTf) * (N_NODES / 8) + hTq]);
    uint4 hv1 = __ldg(&hTg[(head * 128 + hTf + 64) * (N_NODES / 8) + hTq]);
    __syncthreads();
    buildP(0, 0, mreg);
    *(uint4*)&H2[0][hTf * PST + hTq * 4]        = hv0;
    *(uint4*)&H2[0][(hTf + 64) * PST + hTq * 4] = hv1;
    if (t < 32) {
        float4 c4 = __ldg(&g_cj4[head * N_NODES + 32 + t]);
        cjx[1][t] = c4.x; cja[1][t] = c4.y; cjb[1][t] = c4.z;
    }
    mreg = __ldg(&g_maskT[1 * N_NODES + n0 + r]);                  // mask(1)
    __syncthreads();

    for (int tile = 0; tile < T; ++tile) {
        const unsigned mo = (tile & 1) ? BUFB : 0u;
        const int nb = (tile + 1) & 1;
        uint4 nhv0, nhv1; float4 cjn; unsigned mn = 0;
        const bool more = (tile + 1 < T);
        if (more) {
            const int m1q = ((tile + 1) * 32) >> 3;
            nhv0 = __ldg(&hTg[(head * 128 + hTf) * (N_NODES / 8) + m1q + hTq]);
            nhv1 = __ldg(&hTg[(head * 128 + hTf + 64) * (N_NODES / 8) + m1q + hTq]);
            if (t < 32 && tile + 2 < T)
                cjn = __ldg(&g_cj4[head * N_NODES + (tile + 2) * 32 + t]);
            if (tile + 2 < T)
                mn = __ldg(&g_maskT[(tile + 2) * N_NODES + n0 + r]);
            buildP(tile + 1, nb, mreg);
        }

        // ---- mma(tile) ----------------------------------------------------
#pragma unroll
        for (int ks = 0; ks < 2; ks++) {
            unsigned af0[4], af1[4];
            ldmatrix_x4(af0, aaddr[0][ks] + mo);
            ldmatrix_x4(af1, aaddr[1][ks] + mo);
            unsigned b0a[4], b0b[4], b1a[4], b1b[4];
            ldmatrix_x4(b0a, baddr[ks][0][0] + mo);
            ldmatrix_x4(b0b, baddr[ks][0][1] + mo);
            ldmatrix_x4(b1a, baddr[ks][1][0] + mo);
            ldmatrix_x4(b1b, baddr[ks][1][1] + mo);
#pragma unroll
            for (int nt = 0; nt < 8; nt++) {
                unsigned b0 = (nt < 4) ? b0a[nt] : b0b[nt - 4];
                unsigned b1 = (nt < 4) ? b1a[nt] : b1b[nt - 4];
                mma_bf16(acc[0][nt], af0, b0, b1);
                mma_bf16(acc[1][nt], af1, b0, b1);
            }
        }

        if (more) {
            *(uint4*)&H2[nb][hTf * PST + hTq * 4]        = nhv0;
            *(uint4*)&H2[nb][(hTf + 64) * PST + hTq * 4] = nhv1;
            if (t < 32 && tile + 2 < T) {
                cjx[tile & 1][t] = cjn.x;
                cja[tile & 1][t] = cjn.y;
                cjb[tile & 1][t] = cjn.z;
            }
            mreg = mn;
        }
        __syncthreads();
    }

    sum_s[half][r] = rsum;
    __syncthreads();

    // ---- epilogue: out = att * inv (streaming stores) ----------------------
#pragma unroll
    for (int mt = 0; mt < 2; mt++) {
        const int rl0 = warp_m + mt * 16 + g;
        const int rl1 = rl0 + 8;
        const float inv0 = 1.f / (sum_s[0][rl0] + sum_s[1][rl0]);
        const float inv1 = 1.f / (sum_s[0][rl1] + sum_s[1][rl1]);
#pragma unroll
        for (int nt = 0; nt < 8; nt++) {
            const int col = head * HEAD_F + warp_n + nt * 8 + 2 * tig;
            *(float2*)&out[(n0 + rl0) * OUT_F + col] =
                make_float2(acc[mt][nt][0] * inv0, acc[mt][nt][1] * inv0);
            *(float2*)&out[(n0 + rl1) * OUT_F + col] =
                make_float2(acc[mt][nt][2] * inv1, acc[mt][nt][3] * inv1);
        }
    }
}

// ---------------------------------------------------------------------------
extern "C" void kernel_launch(void* const* d_in, const int* in_sizes, int n_in,
                              void* d_out, int out_size)
{
    const float* x     = (const float*)d_in[0];
    const int*   graph = (const int*)  d_in[1];
    const float* W     = (const float*)d_in[2];
    const float* w_i   = (const float*)d_in[3];
    const float* w_j   = (const float*)d_in[4];
    const float* W_r   = (const float*)d_in[5];
    const float* bias  = (const float*)d_in[6];
    float* out = (float*)d_out;

    xsplit_kernel<<<(N_NODES * IN_F / 2) / 256, 256>>>(x);
    wT_kernel<<<dim3(IN_F / 32, HEAD_F / 32, HEADS), 256>>>(W);
    wrT_kernel<<<dim3(IN_F / 32, OUT_F / 32), 256>>>(W_r);
    maskt_kernel<<<dim3(N_NODES / 32, 4), 256>>>(graph);
    gemm_bf16_kernel<<<dim3(N_NODES / 128, HEADS), 256>>>();
    hT_kernel<<<dim3(N_NODES / 32, OUT_F / 32), 256>>>();
    coe_kernel<<<dim3(N_NODES / 8, HEADS), 256>>>(w_i, w_j);
    attn_kernel<<<dim3(N_NODES / 128, HEADS), 256>>>(out);
    res_kernel<<<dim3(N_NODES / 128, HEADS), 256>>>(bias, out);
}